// round 1
// baseline (speedup 1.0000x reference)
#include <cuda_runtime.h>
#include <cuda_bf16.h>
#include <math.h>

// ---------------------------------------------------------------------------
// Problem constants
// ---------------------------------------------------------------------------
#define B       2
#define C_DIM   64
#define H_IMG   128
#define W_IMG   128
#define HW      (H_IMG * W_IMG)          // 16384
#define HEADS   8
#define DIM_HEAD 64
#define INNER   (HEADS * DIM_HEAD)       // 512
#define Q_L     16
#define KV_L    48
#define LN_EPS  1e-5f

// ---------------------------------------------------------------------------
// Scratch buffers (__device__ globals; allocation is forbidden)
// ---------------------------------------------------------------------------
__device__ float g_qn [B * C_DIM * HW];            //  8.4 MB  layernormed q
__device__ float g_kvn[B * 3 * C_DIM * HW];        // 25.2 MB  warped+ln kv
__device__ float g_q  [B * INNER * HW];            // 67 MB    conv q out
__device__ float g_kv [B * 3 * 2 * INNER * HW];    // 402 MB   conv kv out
__device__ float g_att[B * INNER * HW];            // 67 MB    attention out

// ---------------------------------------------------------------------------
// Kernel 1: LayerNorm over channels for q  (b,1,64,128,128)
// ---------------------------------------------------------------------------
__global__ void ln_q_kernel(const float* __restrict__ q_inp,
                            const float* __restrict__ g,
                            const float* __restrict__ beta,
                            float* __restrict__ out)
{
    int pix = blockIdx.x * blockDim.x + threadIdx.x;   // 0..16383
    if (pix >= HW) return;
    int bb = blockIdx.z;

    const float* base = q_inp + ((size_t)bb * C_DIM) * HW + pix;
    float vals[C_DIM];
    float sum = 0.f;
#pragma unroll
    for (int c = 0; c < C_DIM; c++) { float v = base[(size_t)c * HW]; vals[c] = v; sum += v; }
    float mu = sum * (1.f / C_DIM);
    float var = 0.f;
#pragma unroll
    for (int c = 0; c < C_DIM; c++) { float d = vals[c] - mu; var += d * d; }
    var *= (1.f / C_DIM);
    float inv = rsqrtf(var + LN_EPS);

    float* ob = out + ((size_t)bb * C_DIM) * HW + pix;
#pragma unroll
    for (int c = 0; c < C_DIM; c++)
        ob[(size_t)c * HW] = (vals[c] - mu) * inv * g[c] + beta[c];
}

// ---------------------------------------------------------------------------
// Kernel 2: flow warp (nearest, half-to-even) + stack + LayerNorm for kv
// frames: f=0 warp by flow_f, f=1 identity, f=2 warp by flow_b
// ---------------------------------------------------------------------------
__global__ void warp_ln_kv_kernel(const float* __restrict__ k_inp,
                                  const float* __restrict__ flow_f,
                                  const float* __restrict__ flow_b,
                                  const float* __restrict__ g,
                                  const float* __restrict__ beta,
                                  float* __restrict__ out)
{
    int pix = blockIdx.x * blockDim.x + threadIdx.x;
    if (pix >= HW) return;
    int f  = blockIdx.y;   // 0..2
    int bb = blockIdx.z;   // 0..1
    int y = pix >> 7, x = pix & 127;

    int src = pix;
    bool valid = true;
    if (f != 1) {
        const float* fl = (f == 0) ? flow_f : flow_b;
        float fx = fl[((size_t)bb * 2 + 0) * HW + pix];
        float fy = fl[((size_t)bb * 2 + 1) * HW + pix];
        float px = (float)x + fx;
        float py = (float)y + fy;
        int ix = (int)rintf(px);   // round half to even, matches jnp.round
        int iy = (int)rintf(py);
        valid = (ix >= 0) && (ix < W_IMG) && (iy >= 0) && (iy < H_IMG);
        int cx = min(max(ix, 0), W_IMG - 1);
        int cy = min(max(iy, 0), H_IMG - 1);
        src = cy * W_IMG + cx;
    }

    const float* base = k_inp + (((size_t)bb * 3 + f) * C_DIM) * HW + src;
    float vals[C_DIM];
    float sum = 0.f;
#pragma unroll
    for (int c = 0; c < C_DIM; c++) {
        float v = valid ? base[(size_t)c * HW] : 0.f;
        vals[c] = v; sum += v;
    }
    float mu = sum * (1.f / C_DIM);
    float var = 0.f;
#pragma unroll
    for (int c = 0; c < C_DIM; c++) { float d = vals[c] - mu; var += d * d; }
    var *= (1.f / C_DIM);
    float inv = rsqrtf(var + LN_EPS);

    float* ob = out + (((size_t)bb * 3 + f) * C_DIM) * HW + pix;
#pragma unroll
    for (int c = 0; c < C_DIM; c++)
        ob[(size_t)c * HW] = (vals[c] - mu) * inv * g[c] + beta[c];
}

// ---------------------------------------------------------------------------
// Kernel 3: tiled direct 3x3 conv, SAME padding, fp32.
// Block: 256 threads = 32 (x) * 8 (y-groups); each thread: TYP rows x OC_TILE
// output channels. Input channels chunked by IC_CHUNK=8 through SMEM.
// ---------------------------------------------------------------------------
#define IC_CHUNK 8

template <int OC_TILE, int TYP>
__global__ void conv3x3_kernel(const float* __restrict__ in,
                               const float* __restrict__ W,
                               float* __restrict__ out,
                               int IC, int OC)
{
    const int TILE_X = 32;
    const int TILE_Y = 8 * TYP;
    const int SY = TILE_Y + 2;
    const int SX = TILE_X + 2;               // 34

    __shared__ float s_in[IC_CHUNK * SY * SX];
    __shared__ float s_w [OC_TILE * IC_CHUNK * 9];

    int tid = threadIdx.x;                   // 0..255
    int img = blockIdx.z;
    int oc0 = blockIdx.y * OC_TILE;
    const int tiles_x = W_IMG / TILE_X;      // 4
    int tx0 = (blockIdx.x % tiles_x) * TILE_X;
    int ty0 = (blockIdx.x / tiles_x) * TILE_Y;
    int lx  = tid & 31;
    int lyq = tid >> 5;                      // 0..7

    float acc[TYP][OC_TILE];
#pragma unroll
    for (int p = 0; p < TYP; p++)
#pragma unroll
        for (int o = 0; o < OC_TILE; o++) acc[p][o] = 0.f;

    const int IN_ELEMS = IC_CHUNK * SY * SX;
    const int W_ELEMS  = OC_TILE * IC_CHUNK * 9;

    for (int c0 = 0; c0 < IC; c0 += IC_CHUNK) {
        __syncthreads();
        // ---- load input tile (with SAME-pad zeros) ----
        for (int idx = tid; idx < IN_ELEMS; idx += 256) {
            int ic  = idx / (SY * SX);
            int rem = idx % (SY * SX);
            int row = rem / SX, col = rem % SX;
            int gy = ty0 + row - 1;
            int gx = tx0 + col - 1;
            float v = 0.f;
            if (gy >= 0 && gy < H_IMG && gx >= 0 && gx < W_IMG)
                v = in[(((size_t)img * IC + c0 + ic) * H_IMG + gy) * W_IMG + gx];
            s_in[idx] = v;
        }
        // ---- load weight tile ----
        for (int idx = tid; idx < W_ELEMS; idx += 256) {
            int o   = idx / (IC_CHUNK * 9);
            int rem = idx % (IC_CHUNK * 9);
            int ic  = rem / 9, tap = rem % 9;
            s_w[idx] = W[(((size_t)(oc0 + o)) * IC + c0 + ic) * 9 + tap];
        }
        __syncthreads();

        // ---- compute ----
        for (int ic = 0; ic < IC_CHUNK; ic++) {
#pragma unroll
            for (int tap = 0; tap < 9; tap++) {
                const int dy = tap / 3, dx = tap % 3;
                float wreg[OC_TILE];
#pragma unroll
                for (int o = 0; o < OC_TILE; o++)
                    wreg[o] = s_w[(o * IC_CHUNK + ic) * 9 + tap];
#pragma unroll
                for (int p = 0; p < TYP; p++) {
                    float v = s_in[(ic * SY + lyq * TYP + p + dy) * SX + lx + dx];
#pragma unroll
                    for (int o = 0; o < OC_TILE; o++)
                        acc[p][o] = fmaf(v, wreg[o], acc[p][o]);
                }
            }
        }
    }

    // ---- write ----
#pragma unroll
    for (int p = 0; p < TYP; p++) {
        int gy = ty0 + lyq * TYP + p;
#pragma unroll
        for (int o = 0; o < OC_TILE; o++)
            out[(((size_t)img * OC + oc0 + o) * H_IMG + gy) * W_IMG + tx0 + lx] = acc[p][o];
    }
}

// ---------------------------------------------------------------------------
// Kernel 4: windowed attention. One block per (window, head), 128 threads.
// q: (B, 512, 128, 128); kv: (B*3, 1024, 128, 128) with k = ch[0:512],
// v = ch[512:1024]; out -> g_att (B, 512, 128, 128).
// ---------------------------------------------------------------------------
__global__ void attn_kernel(const float* __restrict__ q,
                            const float* __restrict__ kv,
                            const float* __restrict__ stat,
                            float* __restrict__ outp)
{
    int win = blockIdx.x;         // 0..1023
    int hh  = blockIdx.y;         // 0..7
    int bb  = blockIdx.z;         // 0..1
    int wy = win >> 5, wx = win & 31;

    __shared__ float sq[Q_L][DIM_HEAD + 1];
    __shared__ float sk[KV_L][DIM_HEAD + 1];
    __shared__ float sv[KV_L][DIM_HEAD + 1];
    __shared__ float ssim[Q_L][KV_L + 1];

    int tid = threadIdx.x;        // 0..127

    // load q (scaled by 1/sqrt(64) = 0.125)
    for (int i = tid; i < Q_L * DIM_HEAD; i += 128) {
        int pi = i >> 6, d = i & 63;
        int py = pi >> 2, px = pi & 3;
        int y = wy * 4 + py, x = wx * 4 + px;
        sq[pi][d] = q[(((size_t)bb * INNER + hh * DIM_HEAD + d) * H_IMG + y) * W_IMG + x] * 0.125f;
    }
    // load k, v
    for (int i = tid; i < KV_L * DIM_HEAD; i += 128) {
        int j = i >> 6, d = i & 63;
        int f = j >> 4, pi = j & 15;
        int py = pi >> 2, px = pi & 3;
        int y = wy * 4 + py, x = wx * 4 + px;
        size_t base = (((size_t)(bb * 3 + f) * 2 * INNER + hh * DIM_HEAD + d) * H_IMG + y) * W_IMG + x;
        sk[j][d] = kv[base];
        sv[j][d] = kv[base + (size_t)INNER * HW];
    }
    __syncthreads();

    // sim = q @ k^T + static_a
    for (int e = tid; e < Q_L * KV_L; e += 128) {
        int i = e / KV_L, j = e % KV_L;
        float s = 0.f;
#pragma unroll
        for (int d = 0; d < DIM_HEAD; d++) s += sq[i][d] * sk[j][d];
        ssim[i][j] = s + stat[((size_t)hh * Q_L + i) * KV_L + j];
    }
    __syncthreads();

    // softmax over j (one row per thread, 16 rows)
    if (tid < Q_L) {
        float m = -1e30f;
        for (int j = 0; j < KV_L; j++) m = fmaxf(m, ssim[tid][j]);
        float ssum = 0.f;
        for (int j = 0; j < KV_L; j++) {
            float e = expf(ssim[tid][j] - m);
            ssim[tid][j] = e; ssum += e;
        }
        float inv = 1.f / ssum;
        for (int j = 0; j < KV_L; j++) ssim[tid][j] *= inv;
    }
    __syncthreads();

    // out = attn @ v
    for (int e = tid; e < Q_L * DIM_HEAD; e += 128) {
        int i = e >> 6, d = e & 63;
        float s = 0.f;
#pragma unroll
        for (int j = 0; j < KV_L; j++) s += ssim[i][j] * sv[j][d];
        int py = i >> 2, px = i & 3;
        int y = wy * 4 + py, x = wx * 4 + px;
        outp[(((size_t)bb * INNER + hh * DIM_HEAD + d) * H_IMG + y) * W_IMG + x] = s;
    }
}

// ---------------------------------------------------------------------------
// Host launch
// ---------------------------------------------------------------------------
extern "C" void kernel_launch(void* const* d_in, const int* in_sizes, int n_in,
                              void* d_out, int out_size)
{
    (void)in_sizes; (void)n_in; (void)out_size;

    const float* q_inp   = (const float*)d_in[0];
    const float* k_inp   = (const float*)d_in[1];
    const float* flow_f  = (const float*)d_in[2];
    const float* flow_b  = (const float*)d_in[3];
    const float* gq      = (const float*)d_in[4];
    const float* bq      = (const float*)d_in[5];
    const float* gkv     = (const float*)d_in[6];
    const float* bkv     = (const float*)d_in[7];
    const float* Wq      = (const float*)d_in[8];
    const float* Wkv     = (const float*)d_in[9];
    const float* Wout    = (const float*)d_in[10];
    const float* statica = (const float*)d_in[11];

    float *qn, *kvn, *qb, *kvb, *attb;
    cudaGetSymbolAddress((void**)&qn,   g_qn);
    cudaGetSymbolAddress((void**)&kvn,  g_kvn);
    cudaGetSymbolAddress((void**)&qb,   g_q);
    cudaGetSymbolAddress((void**)&kvb,  g_kv);
    cudaGetSymbolAddress((void**)&attb, g_att);

    // 1) layernorm q
    ln_q_kernel<<<dim3(HW / 256, 1, B), 256>>>(q_inp, gq, bq, qn);

    // 2) warp + stack + layernorm kv
    warp_ln_kv_kernel<<<dim3(HW / 256, 3, B), 256>>>(k_inp, flow_f, flow_b, gkv, bkv, kvn);

    // 3) conv q: 64 -> 512, 2 images.  tile 32x32 px, 16 oc / block
    conv3x3_kernel<16, 4><<<dim3(16, INNER / 16, B), 256>>>(qn, Wq, qb, C_DIM, INNER);

    // 4) conv kv: 64 -> 1024, 6 images
    conv3x3_kernel<16, 4><<<dim3(16, (2 * INNER) / 16, B * 3), 256>>>(kvn, Wkv, kvb, C_DIM, 2 * INNER);

    // 5) attention: 1024 windows x 8 heads x 2 batch
    attn_kernel<<<dim3(1024, HEADS, B), 128>>>(qb, kvb, statica, attb);

    // 6) conv out: 512 -> 64, 2 images. tile 32x16 px, 8 oc / block
    conv3x3_kernel<8, 2><<<dim3(32, C_DIM / 8, B), 256>>>(attb, Wout, (float*)d_out, INNER, C_DIM);
}

// round 2
// speedup vs baseline: 1.0280x; 1.0280x over previous
#include <cuda_runtime.h>
#include <cuda_bf16.h>
#include <math.h>

// ---------------------------------------------------------------------------
// Problem constants
// ---------------------------------------------------------------------------
#define B       2
#define C_DIM   64
#define H_IMG   128
#define W_IMG   128
#define HW      (H_IMG * W_IMG)          // 16384
#define HEADS   8
#define DIM_HEAD 64
#define INNER   (HEADS * DIM_HEAD)       // 512
#define Q_L     16
#define KV_L    48
#define LN_EPS  1e-5f

// ---------------------------------------------------------------------------
// Scratch buffers (__device__ globals; allocation is forbidden)
// ---------------------------------------------------------------------------
__device__ float g_qn [B * C_DIM * HW];            //  8.4 MB  layernormed q
__device__ float g_kvn[B * 3 * C_DIM * HW];        // 25.2 MB  warped+ln kv
__device__ float g_q  [B * INNER * HW];            // 67 MB    conv q out
__device__ float g_kv [B * 3 * 2 * INNER * HW];    // 402 MB   conv kv out
__device__ float g_att[B * INNER * HW];            // 67 MB    attention out

// ---------------------------------------------------------------------------
// packed fp32x2 FMA (sm_100+; ptxas never emits this from C++)
// ---------------------------------------------------------------------------
__device__ __forceinline__ void ffma2(unsigned long long& acc,
                                      unsigned long long a,
                                      unsigned long long b)
{
    asm("fma.rn.f32x2 %0, %1, %2, %0;" : "+l"(acc) : "l"(a), "l"(b));
}

// ---------------------------------------------------------------------------
// Kernel 1: LayerNorm over channels for q  (b,1,64,128,128)
// ---------------------------------------------------------------------------
__global__ void ln_q_kernel(const float* __restrict__ q_inp,
                            const float* __restrict__ g,
                            const float* __restrict__ beta,
                            float* __restrict__ out)
{
    int pix = blockIdx.x * blockDim.x + threadIdx.x;   // 0..16383
    if (pix >= HW) return;
    int bb = blockIdx.z;

    const float* base = q_inp + ((size_t)bb * C_DIM) * HW + pix;
    float vals[C_DIM];
    float sum = 0.f;
#pragma unroll
    for (int c = 0; c < C_DIM; c++) { float v = base[(size_t)c * HW]; vals[c] = v; sum += v; }
    float mu = sum * (1.f / C_DIM);
    float var = 0.f;
#pragma unroll
    for (int c = 0; c < C_DIM; c++) { float d = vals[c] - mu; var += d * d; }
    var *= (1.f / C_DIM);
    float inv = rsqrtf(var + LN_EPS);

    float* ob = out + ((size_t)bb * C_DIM) * HW + pix;
#pragma unroll
    for (int c = 0; c < C_DIM; c++)
        ob[(size_t)c * HW] = (vals[c] - mu) * inv * g[c] + beta[c];
}

// ---------------------------------------------------------------------------
// Kernel 2: flow warp (nearest, half-to-even) + stack + LayerNorm for kv
// ---------------------------------------------------------------------------
__global__ void warp_ln_kv_kernel(const float* __restrict__ k_inp,
                                  const float* __restrict__ flow_f,
                                  const float* __restrict__ flow_b,
                                  const float* __restrict__ g,
                                  const float* __restrict__ beta,
                                  float* __restrict__ out)
{
    int pix = blockIdx.x * blockDim.x + threadIdx.x;
    if (pix >= HW) return;
    int f  = blockIdx.y;   // 0..2
    int bb = blockIdx.z;   // 0..1
    int y = pix >> 7, x = pix & 127;

    int src = pix;
    bool valid = true;
    if (f != 1) {
        const float* fl = (f == 0) ? flow_f : flow_b;
        float fx = fl[((size_t)bb * 2 + 0) * HW + pix];
        float fy = fl[((size_t)bb * 2 + 1) * HW + pix];
        float px = (float)x + fx;
        float py = (float)y + fy;
        int ix = (int)rintf(px);   // round half to even, matches jnp.round
        int iy = (int)rintf(py);
        valid = (ix >= 0) && (ix < W_IMG) && (iy >= 0) && (iy < H_IMG);
        int cx = min(max(ix, 0), W_IMG - 1);
        int cy = min(max(iy, 0), H_IMG - 1);
        src = cy * W_IMG + cx;
    }

    const float* base = k_inp + (((size_t)bb * 3 + f) * C_DIM) * HW + src;
    float vals[C_DIM];
    float sum = 0.f;
#pragma unroll
    for (int c = 0; c < C_DIM; c++) {
        float v = valid ? base[(size_t)c * HW] : 0.f;
        vals[c] = v; sum += v;
    }
    float mu = sum * (1.f / C_DIM);
    float var = 0.f;
#pragma unroll
    for (int c = 0; c < C_DIM; c++) { float d = vals[c] - mu; var += d * d; }
    var *= (1.f / C_DIM);
    float inv = rsqrtf(var + LN_EPS);

    float* ob = out + (((size_t)bb * 3 + f) * C_DIM) * HW + pix;
#pragma unroll
    for (int c = 0; c < C_DIM; c++)
        ob[(size_t)c * HW] = (vals[c] - mu) * inv * g[c] + beta[c];
}

// ---------------------------------------------------------------------------
// Kernel 3: tiled direct 3x3 conv using packed f32x2 FMAs.
// Block: 256 threads = 32 x-threads (each owns a pixel PAIR -> 64 px wide)
//        x 8 y-groups x TYP rows. OC_TILE output channels per block.
// Weights staged in SMEM duplicated as float2(w,w) so one broadcast LDS.64
// feeds the packed FMA directly.
// ---------------------------------------------------------------------------
#define IC_CHUNK 8

template <int OC_TILE, int TYP>
__global__ __launch_bounds__(256, 2)
void conv3x3_p2_kernel(const float* __restrict__ in,
                       const float* __restrict__ W,
                       float* __restrict__ out,
                       int IC, int OC)
{
    const int TILE_X = 64;                   // pixels (32 pairs)
    const int TILE_Y = 8 * TYP;
    const int SY = TILE_Y + 2;
    const int SX = TILE_X + 2;               // 66

    __shared__ float  s_in[IC_CHUNK][SY][SX];
    __shared__ float2 s_w [IC_CHUNK][9][OC_TILE];

    int tid = threadIdx.x;                   // 0..255
    int img = blockIdx.z;
    int oc0 = blockIdx.y * OC_TILE;
    const int tiles_x = W_IMG / TILE_X;      // 2
    int tx0 = (blockIdx.x % tiles_x) * TILE_X;
    int ty0 = (blockIdx.x / tiles_x) * TILE_Y;
    int lx  = tid & 31;                      // pair index: pixels 2lx, 2lx+1
    int lyq = tid >> 5;                      // 0..7

    unsigned long long acc[TYP][OC_TILE];
#pragma unroll
    for (int p = 0; p < TYP; p++)
#pragma unroll
        for (int o = 0; o < OC_TILE; o++) acc[p][o] = 0ull;

    const int IN_ELEMS = IC_CHUNK * SY * SX;
    const int W_ELEMS  = OC_TILE * IC_CHUNK * 9;

    for (int c0 = 0; c0 < IC; c0 += IC_CHUNK) {
        __syncthreads();
        // ---- load input tile (SAME-pad zeros) ----
        for (int idx = tid; idx < IN_ELEMS; idx += 256) {
            int ic  = idx / (SY * SX);
            int rem = idx % (SY * SX);
            int row = rem / SX, col = rem % SX;
            int gy = ty0 + row - 1;
            int gx = tx0 + col - 1;
            float v = 0.f;
            if (gy >= 0 && gy < H_IMG && gx >= 0 && gx < W_IMG)
                v = in[(((size_t)img * IC + c0 + ic) * H_IMG + gy) * W_IMG + gx];
            s_in[ic][row][col] = v;
        }
        // ---- load weights, duplicated into both f32x2 lanes ----
        for (int idx = tid; idx < W_ELEMS; idx += 256) {
            int o   = idx / (IC_CHUNK * 9);
            int rem = idx % (IC_CHUNK * 9);
            int ic  = rem / 9, tap = rem % 9;
            float w = W[(((size_t)(oc0 + o)) * IC + c0 + ic) * 9 + tap];
            s_w[ic][tap][o] = make_float2(w, w);
        }
        __syncthreads();

        // ---- compute ----
#pragma unroll
        for (int ic = 0; ic < IC_CHUNK; ic++) {
#pragma unroll
            for (int dy = 0; dy < 3; dy++) {
                // pixel pairs for the 3 horizontal taps, per row
                unsigned long long pr[TYP][3];
#pragma unroll
                for (int p = 0; p < TYP; p++) {
                    const float* rp = &s_in[ic][lyq * TYP + p + dy][2 * lx];
                    unsigned long long p0 = *(const unsigned long long*)(rp);     // v0,v1
                    unsigned long long p2 = *(const unsigned long long*)(rp + 2); // v2,v3
                    pr[p][0] = p0;
                    pr[p][2] = p2;
                    pr[p][1] = (p0 >> 32) | (p2 << 32);                           // v1,v2
                }
#pragma unroll
                for (int dx = 0; dx < 3; dx++) {
                    const int tap = dy * 3 + dx;
#pragma unroll
                    for (int o = 0; o < OC_TILE; o++) {
                        unsigned long long wp =
                            *(const unsigned long long*)&s_w[ic][tap][o];
#pragma unroll
                        for (int p = 0; p < TYP; p++)
                            ffma2(acc[p][o], pr[p][dx], wp);
                    }
                }
            }
        }
    }

    // ---- write (pixel pairs, 8B stores) ----
#pragma unroll
    for (int p = 0; p < TYP; p++) {
        int gy = ty0 + lyq * TYP + p;
#pragma unroll
        for (int o = 0; o < OC_TILE; o++) {
            float2 r;
            r.x = __uint_as_float((unsigned)(acc[p][o] & 0xffffffffull));
            r.y = __uint_as_float((unsigned)(acc[p][o] >> 32));
            *(float2*)&out[(((size_t)img * OC + oc0 + o) * H_IMG + gy) * W_IMG
                           + tx0 + 2 * lx] = r;
        }
    }
}

// ---------------------------------------------------------------------------
// Kernel 4: windowed attention. One block per (window, head), 128 threads.
// ---------------------------------------------------------------------------
__global__ void attn_kernel(const float* __restrict__ q,
                            const float* __restrict__ kv,
                            const float* __restrict__ stat,
                            float* __restrict__ outp)
{
    int win = blockIdx.x;         // 0..1023
    int hh  = blockIdx.y;         // 0..7
    int bb  = blockIdx.z;         // 0..1
    int wy = win >> 5, wx = win & 31;

    __shared__ float sq[Q_L][DIM_HEAD + 1];
    __shared__ float sk[KV_L][DIM_HEAD + 1];
    __shared__ float sv[KV_L][DIM_HEAD + 1];
    __shared__ float ssim[Q_L][KV_L + 1];

    int tid = threadIdx.x;        // 0..127

    for (int i = tid; i < Q_L * DIM_HEAD; i += 128) {
        int pi = i >> 6, d = i & 63;
        int py = pi >> 2, px = pi & 3;
        int y = wy * 4 + py, x = wx * 4 + px;
        sq[pi][d] = q[(((size_t)bb * INNER + hh * DIM_HEAD + d) * H_IMG + y) * W_IMG + x] * 0.125f;
    }
    for (int i = tid; i < KV_L * DIM_HEAD; i += 128) {
        int j = i >> 6, d = i & 63;
        int f = j >> 4, pi = j & 15;
        int py = pi >> 2, px = pi & 3;
        int y = wy * 4 + py, x = wx * 4 + px;
        size_t base = (((size_t)(bb * 3 + f) * 2 * INNER + hh * DIM_HEAD + d) * H_IMG + y) * W_IMG + x;
        sk[j][d] = kv[base];
        sv[j][d] = kv[base + (size_t)INNER * HW];
    }
    __syncthreads();

    for (int e = tid; e < Q_L * KV_L; e += 128) {
        int i = e / KV_L, j = e % KV_L;
        float s = 0.f;
#pragma unroll
        for (int d = 0; d < DIM_HEAD; d++) s += sq[i][d] * sk[j][d];
        ssim[i][j] = s + stat[((size_t)hh * Q_L + i) * KV_L + j];
    }
    __syncthreads();

    if (tid < Q_L) {
        float m = -1e30f;
        for (int j = 0; j < KV_L; j++) m = fmaxf(m, ssim[tid][j]);
        float ssum = 0.f;
        for (int j = 0; j < KV_L; j++) {
            float e = expf(ssim[tid][j] - m);
            ssim[tid][j] = e; ssum += e;
        }
        float inv = 1.f / ssum;
        for (int j = 0; j < KV_L; j++) ssim[tid][j] *= inv;
    }
    __syncthreads();

    for (int e = tid; e < Q_L * DIM_HEAD; e += 128) {
        int i = e >> 6, d = e & 63;
        float s = 0.f;
#pragma unroll
        for (int j = 0; j < KV_L; j++) s += ssim[i][j] * sv[j][d];
        int py = i >> 2, px = i & 3;
        int y = wy * 4 + py, x = wx * 4 + px;
        outp[(((size_t)bb * INNER + hh * DIM_HEAD + d) * H_IMG + y) * W_IMG + x] = s;
    }
}

// ---------------------------------------------------------------------------
// Host launch
// ---------------------------------------------------------------------------
extern "C" void kernel_launch(void* const* d_in, const int* in_sizes, int n_in,
                              void* d_out, int out_size)
{
    (void)in_sizes; (void)n_in; (void)out_size;

    const float* q_inp   = (const float*)d_in[0];
    const float* k_inp   = (const float*)d_in[1];
    const float* flow_f  = (const float*)d_in[2];
    const float* flow_b  = (const float*)d_in[3];
    const float* gq      = (const float*)d_in[4];
    const float* bq      = (const float*)d_in[5];
    const float* gkv     = (const float*)d_in[6];
    const float* bkv     = (const float*)d_in[7];
    const float* Wq      = (const float*)d_in[8];
    const float* Wkv     = (const float*)d_in[9];
    const float* Wout    = (const float*)d_in[10];
    const float* statica = (const float*)d_in[11];

    float *qn, *kvn, *qb, *kvb, *attb;
    cudaGetSymbolAddress((void**)&qn,   g_qn);
    cudaGetSymbolAddress((void**)&kvn,  g_kvn);
    cudaGetSymbolAddress((void**)&qb,   g_q);
    cudaGetSymbolAddress((void**)&kvb,  g_kv);
    cudaGetSymbolAddress((void**)&attb, g_att);

    // 1) layernorm q
    ln_q_kernel<<<dim3(HW / 256, 1, B), 256>>>(q_inp, gq, bq, qn);

    // 2) warp + stack + layernorm kv
    warp_ln_kv_kernel<<<dim3(HW / 256, 3, B), 256>>>(k_inp, flow_f, flow_b, gkv, bkv, kvn);

    // 3) conv q: 64 -> 512, 2 images. tile 64x16 px, 16 oc / block
    conv3x3_p2_kernel<16, 2><<<dim3(16, INNER / 16, B), 256>>>(qn, Wq, qb, C_DIM, INNER);

    // 4) conv kv: 64 -> 1024, 6 images
    conv3x3_p2_kernel<16, 2><<<dim3(16, (2 * INNER) / 16, B * 3), 256>>>(kvn, Wkv, kvb, C_DIM, 2 * INNER);

    // 5) attention: 1024 windows x 8 heads x 2 batch
    attn_kernel<<<dim3(1024, HEADS, B), 128>>>(qb, kvb, statica, attb);

    // 6) conv out: 512 -> 64, 2 images. tile 64x16 px, 8 oc / block (256 blocks)
    conv3x3_p2_kernel<8, 2><<<dim3(16, C_DIM / 8, B), 256>>>(attb, Wout, (float*)d_out, INNER, C_DIM);
}

// round 4
// speedup vs baseline: 1.5812x; 1.5382x over previous
#include <cuda_runtime.h>
#include <cuda_bf16.h>
#include <mma.h>
#include <math.h>
#include <stdint.h>

using namespace nvcuda;

// ---------------------------------------------------------------------------
// Problem constants
// ---------------------------------------------------------------------------
#define B       2
#define C_DIM   64
#define H_IMG   128
#define W_IMG   128
#define HW      (H_IMG * W_IMG)          // 16384
#define HEADS   8
#define DIM_HEAD 64
#define INNER   (HEADS * DIM_HEAD)       // 512
#define Q_L     16
#define KV_L    48
#define LN_EPS  1e-5f

// ---------------------------------------------------------------------------
// Scratch buffers (__device__ globals; allocation is forbidden)
// NHWC for conv inputs, NCHW for conv outputs.
// ---------------------------------------------------------------------------
__device__ float g_qn  [B * HW * C_DIM];             // LN(q), NHWC
__device__ float g_kvn [B * 3 * HW * C_DIM];         // warped+LN kv, NHWC
__device__ float g_q   [B * INNER * HW];             // conv q out, NCHW
__device__ float g_kv  [B * 3 * 2 * INNER * HW];     // conv kv out, NCHW
__device__ float g_att [B * HW * INNER];             // attention out, NHWC
__device__ float g_wt_q  [9 * INNER * C_DIM];        // Wq  as [tap][oc][ic]
__device__ float g_wt_kv [9 * 2 * INNER * C_DIM];    // Wkv as [tap][oc][ic]
__device__ float g_wt_out[9 * C_DIM * INNER];        // Wout as [tap][oc][ic]

// ---------------------------------------------------------------------------
// tf32 round (rna) — plain sm_80+ PTX, no arch-suffix feature
// ---------------------------------------------------------------------------
__device__ __forceinline__ float tf32r(float x) {
    uint32_t o;
    asm("cvt.rna.tf32.f32 %0, %1;" : "=r"(o) : "f"(x));
    return __uint_as_float(o);
}

// ---------------------------------------------------------------------------
// Kernel 0: weight transform  W[oc][ic][3][3] -> Wt[tap][oc][ic]
// ---------------------------------------------------------------------------
__global__ void wtrans_kernel(const float* __restrict__ W,
                              float* __restrict__ Wt, int OC, int IC)
{
    int idx = blockIdx.x * blockDim.x + threadIdx.x;
    if (idx >= OC * IC) return;
    int oc = idx / IC, ic = idx % IC;
    const float* src = W + ((size_t)oc * IC + ic) * 9;
#pragma unroll
    for (int t = 0; t < 9; t++)
        Wt[((size_t)t * OC + oc) * IC + ic] = src[t];
}

// ---------------------------------------------------------------------------
// Kernel 1: LayerNorm q -> NHWC
// ---------------------------------------------------------------------------
__global__ void ln_q_kernel(const float* __restrict__ q_inp,
                            const float* __restrict__ g,
                            const float* __restrict__ beta,
                            float* __restrict__ out)
{
    int pix = blockIdx.x * blockDim.x + threadIdx.x;
    if (pix >= HW) return;
    int bb = blockIdx.z;

    const float* base = q_inp + ((size_t)bb * C_DIM) * HW + pix;
    float vals[C_DIM];
    float sum = 0.f;
#pragma unroll
    for (int c = 0; c < C_DIM; c++) { float v = base[(size_t)c * HW]; vals[c] = v; sum += v; }
    float mu = sum * (1.f / C_DIM);
    float var = 0.f;
#pragma unroll
    for (int c = 0; c < C_DIM; c++) { float d = vals[c] - mu; var += d * d; }
    var *= (1.f / C_DIM);
    float inv = rsqrtf(var + LN_EPS);

    float* ob = out + ((size_t)bb * HW + pix) * C_DIM;
#pragma unroll
    for (int c = 0; c < C_DIM; c++)
        vals[c] = (vals[c] - mu) * inv * g[c] + beta[c];
#pragma unroll
    for (int c = 0; c < C_DIM; c += 4)
        *(float4*)&ob[c] = make_float4(vals[c], vals[c+1], vals[c+2], vals[c+3]);
}

// ---------------------------------------------------------------------------
// Kernel 2: flow warp + stack + LayerNorm kv -> NHWC
// ---------------------------------------------------------------------------
__global__ void warp_ln_kv_kernel(const float* __restrict__ k_inp,
                                  const float* __restrict__ flow_f,
                                  const float* __restrict__ flow_b,
                                  const float* __restrict__ g,
                                  const float* __restrict__ beta,
                                  float* __restrict__ out)
{
    int pix = blockIdx.x * blockDim.x + threadIdx.x;
    if (pix >= HW) return;
    int f  = blockIdx.y;   // 0..2
    int bb = blockIdx.z;   // 0..1
    int y = pix >> 7, x = pix & 127;

    int src = pix;
    bool valid = true;
    if (f != 1) {
        const float* fl = (f == 0) ? flow_f : flow_b;
        float fx = fl[((size_t)bb * 2 + 0) * HW + pix];
        float fy = fl[((size_t)bb * 2 + 1) * HW + pix];
        int ix = (int)rintf((float)x + fx);
        int iy = (int)rintf((float)y + fy);
        valid = (ix >= 0) && (ix < W_IMG) && (iy >= 0) && (iy < H_IMG);
        int cx = min(max(ix, 0), W_IMG - 1);
        int cy = min(max(iy, 0), H_IMG - 1);
        src = cy * W_IMG + cx;
    }

    const float* base = k_inp + (((size_t)bb * 3 + f) * C_DIM) * HW + src;
    float vals[C_DIM];
    float sum = 0.f;
#pragma unroll
    for (int c = 0; c < C_DIM; c++) {
        float v = valid ? base[(size_t)c * HW] : 0.f;
        vals[c] = v; sum += v;
    }
    float mu = sum * (1.f / C_DIM);
    float var = 0.f;
#pragma unroll
    for (int c = 0; c < C_DIM; c++) { float d = vals[c] - mu; var += d * d; }
    var *= (1.f / C_DIM);
    float inv = rsqrtf(var + LN_EPS);

    float* ob = out + (((size_t)(bb * 3 + f)) * HW + pix) * C_DIM;
#pragma unroll
    for (int c = 0; c < C_DIM; c++)
        vals[c] = (vals[c] - mu) * inv * g[c] + beta[c];
#pragma unroll
    for (int c = 0; c < C_DIM; c += 4)
        *(float4*)&ob[c] = make_float4(vals[c], vals[c+1], vals[c+2], vals[c+3]);
}

// ---------------------------------------------------------------------------
// Kernel 3: 3x3 conv as implicit GEMM on wmma tf32 (m16n16k8, HMMA pipe).
// One CTA = one image row (M = 128 px) x 64 output channels.
// A: SMEM [3 rows][130 px][68f], tf32-rounded NHWC slice (halo included).
// B: SMEM per-dy [3 dx][64 oc][68f] from Wt[tap][oc][ic].
// 8 warps = 2 (px) x 4 (oc); each warp 64 px x 16 oc = 4 m-frags.
// K loop: ic chunks of 64  x  3 dy  x  3 dx  x  8 k-steps.
// Epilogue: store_matrix_sync col-major straight to NCHW gmem (ldm = HW).
// ---------------------------------------------------------------------------
#define AROW   68
#define APITCH (130 * AROW)                 // floats per staged input row
#define A_ELEMS (3 * APITCH)                // 26520 floats
#define B_ELEMS (3 * 64 * AROW)             // 13056 floats
#define CONV_SMEM ((A_ELEMS + B_ELEMS) * 4) // 158304 bytes

template <int N_TILE>
__global__ __launch_bounds__(256, 1)
void conv3x3_wmma_kernel(const float* __restrict__ in,   // NHWC
                         const float* __restrict__ Wt,   // [9][OC][IC]
                         float* __restrict__ out,        // NCHW
                         int IC, int OC)
{
    extern __shared__ float smem[];
    float* sA = smem;                 // [3][130][AROW]
    float* sB = smem + A_ELEMS;       // [3][N_TILE][AROW]

    int tid = threadIdx.x;
    int wid = tid >> 5;

    int y   = blockIdx.x;
    int oc0 = blockIdx.y * N_TILE;
    int img = blockIdx.z;

    int warp_px = wid & 1;            // 0..1  (64 px each)
    int warp_oc = wid >> 1;           // 0..3  (16 oc each)

    wmma::fragment<wmma::accumulator, 16, 16, 8, float> acc[4];
#pragma unroll
    for (int mf = 0; mf < 4; mf++) wmma::fill_fragment(acc[mf], 0.0f);

    const int chunks = IC / 64;

    for (int c = 0; c < chunks; c++) {
        int ic0 = c * 64;

        __syncthreads();
        // ---- stage A: 3 rows x 130 px x 64 ic, tf32-rounded, zero-padded ----
        for (int i = tid; i < 3 * 130 * 16; i += 256) {
            int r   = i / (130 * 16);
            int rem = i % (130 * 16);
            int p   = rem >> 4;
            int f4  = rem & 15;
            int gy = y + r - 1, gx = p - 1;
            float4 v = make_float4(0.f, 0.f, 0.f, 0.f);
            if (gy >= 0 && gy < H_IMG && gx >= 0 && gx < W_IMG)
                v = *(const float4*)&in[(((size_t)img * H_IMG + gy) * W_IMG + gx) * IC + ic0 + f4 * 4];
            v.x = tf32r(v.x); v.y = tf32r(v.y); v.z = tf32r(v.z); v.w = tf32r(v.w);
            *(float4*)&sA[(r * 130 + p) * AROW + f4 * 4] = v;
        }

        for (int dy = 0; dy < 3; dy++) {
            if (dy > 0) __syncthreads();   // protect sB reuse
            // ---- stage B: taps (dy,0..2) x N_TILE oc x 64 ic ----
            for (int i = tid; i < 3 * N_TILE * 16; i += 256) {
                int dx  = i / (N_TILE * 16);
                int rem = i % (N_TILE * 16);
                int o   = rem >> 4;
                int f4  = rem & 15;
                int tap = dy * 3 + dx;
                float4 w = *(const float4*)&Wt[(((size_t)tap * OC) + oc0 + o) * IC + ic0 + f4 * 4];
                w.x = tf32r(w.x); w.y = tf32r(w.y); w.z = tf32r(w.z); w.w = tf32r(w.w);
                *(float4*)&sB[(dx * N_TILE + o) * AROW + f4 * 4] = w;
            }
            __syncthreads();

            // ---- compute ----
#pragma unroll
            for (int dx = 0; dx < 3; dx++) {
#pragma unroll
                for (int s = 0; s < 8; s++) {
                    wmma::fragment<wmma::matrix_b, 16, 16, 8,
                                   wmma::precision::tf32, wmma::col_major> bf;
                    wmma::load_matrix_sync(
                        bf, &sB[(dx * N_TILE + warp_oc * 16) * AROW + s * 8], AROW);
#pragma unroll
                    for (int mf = 0; mf < 4; mf++) {
                        int px = warp_px * 64 + mf * 16;
                        wmma::fragment<wmma::matrix_a, 16, 16, 8,
                                       wmma::precision::tf32, wmma::row_major> af;
                        wmma::load_matrix_sync(
                            af, &sA[(dy * 130 + px + dx) * AROW + s * 8], AROW);
                        wmma::mma_sync(acc[mf], af, bf, acc[mf]);
                    }
                }
            }
        }
    }

    // ---- epilogue: col-major store -> NCHW (ldm = HW between channels) ----
#pragma unroll
    for (int mf = 0; mf < 4; mf++) {
        int px = warp_px * 64 + mf * 16;
        float* dst = &out[(((size_t)img * OC + oc0 + warp_oc * 16) * H_IMG + y) * W_IMG + px];
        wmma::store_matrix_sync(dst, acc[mf], HW, wmma::mem_col_major);
    }
}

// ---------------------------------------------------------------------------
// Kernel 4: windowed attention; q/kv NCHW in, attention out NHWC.
// ---------------------------------------------------------------------------
__global__ void attn_kernel(const float* __restrict__ q,
                            const float* __restrict__ kv,
                            const float* __restrict__ stat,
                            float* __restrict__ outp)
{
    int win = blockIdx.x;         // 0..1023
    int hh  = blockIdx.y;         // 0..7
    int bb  = blockIdx.z;         // 0..1
    int wy = win >> 5, wx = win & 31;

    __shared__ float sq[Q_L][DIM_HEAD + 1];
    __shared__ float sk[KV_L][DIM_HEAD + 1];
    __shared__ float sv[KV_L][DIM_HEAD + 1];
    __shared__ float ssim[Q_L][KV_L + 1];

    int tid = threadIdx.x;        // 0..127

    for (int i = tid; i < Q_L * DIM_HEAD; i += 128) {
        int pi = i >> 6, d = i & 63;
        int py = pi >> 2, px = pi & 3;
        int y = wy * 4 + py, x = wx * 4 + px;
        sq[pi][d] = q[(((size_t)bb * INNER + hh * DIM_HEAD + d) * H_IMG + y) * W_IMG + x] * 0.125f;
    }
    for (int i = tid; i < KV_L * DIM_HEAD; i += 128) {
        int j = i >> 6, d = i & 63;
        int f = j >> 4, pi = j & 15;
        int py = pi >> 2, px = pi & 3;
        int y = wy * 4 + py, x = wx * 4 + px;
        size_t base = (((size_t)(bb * 3 + f) * 2 * INNER + hh * DIM_HEAD + d) * H_IMG + y) * W_IMG + x;
        sk[j][d] = kv[base];
        sv[j][d] = kv[base + (size_t)INNER * HW];
    }
    __syncthreads();

    for (int e = tid; e < Q_L * KV_L; e += 128) {
        int i = e / KV_L, j = e % KV_L;
        float s = 0.f;
#pragma unroll
        for (int d = 0; d < DIM_HEAD; d++) s += sq[i][d] * sk[j][d];
        ssim[i][j] = s + stat[((size_t)hh * Q_L + i) * KV_L + j];
    }
    __syncthreads();

    if (tid < Q_L) {
        float m = -1e30f;
        for (int j = 0; j < KV_L; j++) m = fmaxf(m, ssim[tid][j]);
        float ssum = 0.f;
        for (int j = 0; j < KV_L; j++) {
            float e = expf(ssim[tid][j] - m);
            ssim[tid][j] = e; ssum += e;
        }
        float inv = 1.f / ssum;
        for (int j = 0; j < KV_L; j++) ssim[tid][j] *= inv;
    }
    __syncthreads();

    for (int e = tid; e < Q_L * DIM_HEAD; e += 128) {
        int i = e >> 6, d = e & 63;
        float s = 0.f;
#pragma unroll
        for (int j = 0; j < KV_L; j++) s += ssim[i][j] * sv[j][d];
        int py = i >> 2, px = i & 3;
        int y = wy * 4 + py, x = wx * 4 + px;
        outp[(((size_t)bb * HW) + y * W_IMG + x) * INNER + hh * DIM_HEAD + d] = s;
    }
}

// ---------------------------------------------------------------------------
// Host launch
// ---------------------------------------------------------------------------
extern "C" void kernel_launch(void* const* d_in, const int* in_sizes, int n_in,
                              void* d_out, int out_size)
{
    (void)in_sizes; (void)n_in; (void)out_size;

    const float* q_inp   = (const float*)d_in[0];
    const float* k_inp   = (const float*)d_in[1];
    const float* flow_f  = (const float*)d_in[2];
    const float* flow_b  = (const float*)d_in[3];
    const float* gq      = (const float*)d_in[4];
    const float* bq      = (const float*)d_in[5];
    const float* gkv     = (const float*)d_in[6];
    const float* bkv     = (const float*)d_in[7];
    const float* Wq      = (const float*)d_in[8];
    const float* Wkv     = (const float*)d_in[9];
    const float* Wout    = (const float*)d_in[10];
    const float* statica = (const float*)d_in[11];

    float *qn, *kvn, *qb, *kvb, *attb, *wtq, *wtkv, *wtout;
    cudaGetSymbolAddress((void**)&qn,    g_qn);
    cudaGetSymbolAddress((void**)&kvn,   g_kvn);
    cudaGetSymbolAddress((void**)&qb,    g_q);
    cudaGetSymbolAddress((void**)&kvb,   g_kv);
    cudaGetSymbolAddress((void**)&attb,  g_att);
    cudaGetSymbolAddress((void**)&wtq,   g_wt_q);
    cudaGetSymbolAddress((void**)&wtkv,  g_wt_kv);
    cudaGetSymbolAddress((void**)&wtout, g_wt_out);

    cudaFuncSetAttribute(conv3x3_wmma_kernel<64>,
                         cudaFuncAttributeMaxDynamicSharedMemorySize, CONV_SMEM);

    // 0) weight transforms
    wtrans_kernel<<<(INNER * C_DIM + 255) / 256, 256>>>(Wq, wtq, INNER, C_DIM);
    wtrans_kernel<<<(2 * INNER * C_DIM + 255) / 256, 256>>>(Wkv, wtkv, 2 * INNER, C_DIM);
    wtrans_kernel<<<(C_DIM * INNER + 255) / 256, 256>>>(Wout, wtout, C_DIM, INNER);

    // 1) layernorm q  (NHWC out)
    ln_q_kernel<<<dim3(HW / 256, 1, B), 256>>>(q_inp, gq, bq, qn);

    // 2) warp + stack + layernorm kv  (NHWC out)
    warp_ln_kv_kernel<<<dim3(HW / 256, 3, B), 256>>>(k_inp, flow_f, flow_b, gkv, bkv, kvn);

    // 3) conv q: 64 -> 512
    conv3x3_wmma_kernel<64><<<dim3(H_IMG, INNER / 64, B), 256, CONV_SMEM>>>(
        qn, wtq, qb, C_DIM, INNER);

    // 4) conv kv: 64 -> 1024
    conv3x3_wmma_kernel<64><<<dim3(H_IMG, (2 * INNER) / 64, B * 3), 256, CONV_SMEM>>>(
        kvn, wtkv, kvb, C_DIM, 2 * INNER);

    // 5) attention
    attn_kernel<<<dim3(1024, HEADS, B), 128>>>(qb, kvb, statica, attb);

    // 6) conv out: 512 -> 64  (NHWC in, NCHW out -> d_out)
    conv3x3_wmma_kernel<64><<<dim3(H_IMG, 1, B), 256, CONV_SMEM>>>(
        attb, wtout, (float*)d_out, INNER, C_DIM);
}

// round 5
// speedup vs baseline: 1.9994x; 1.2645x over previous
#include <cuda_runtime.h>
#include <cuda_bf16.h>
#include <mma.h>
#include <math.h>
#include <stdint.h>

using namespace nvcuda;

// ---------------------------------------------------------------------------
// Problem constants
// ---------------------------------------------------------------------------
#define B       2
#define C_DIM   64
#define H_IMG   128
#define W_IMG   128
#define HW      (H_IMG * W_IMG)          // 16384
#define HEADS   8
#define DIM_HEAD 64
#define INNER   (HEADS * DIM_HEAD)       // 512
#define Q_L     16
#define KV_L    48
#define LN_EPS  1e-5f

// ---------------------------------------------------------------------------
// Scratch buffers (__device__ globals; allocation is forbidden)
// conv inputs + conv outputs in NHWC; only final d_out is NCHW.
// ---------------------------------------------------------------------------
__device__ float g_qn  [B * HW * C_DIM];             // LN(q), NHWC (tf32)
__device__ float g_kvn [B * 3 * HW * C_DIM];         // warped+LN kv, NHWC (tf32)
__device__ float g_q   [B * HW * INNER];             // conv q out, NHWC
__device__ float g_kv  [B * 3 * HW * 2 * INNER];     // conv kv out, NHWC
__device__ float g_att [B * HW * INNER];             // attention out, NHWC (tf32)
__device__ float g_wt_q  [9 * INNER * C_DIM];        // Wq  as [tap][oc][ic] (tf32)
__device__ float g_wt_kv [9 * 2 * INNER * C_DIM];    // Wkv as [tap][oc][ic] (tf32)
__device__ float g_wt_out[9 * C_DIM * INNER];        // Wout as [tap][oc][ic] (tf32)

// ---------------------------------------------------------------------------
// tf32 round (rna) — plain sm_80+ PTX
// ---------------------------------------------------------------------------
__device__ __forceinline__ float tf32r(float x) {
    uint32_t o;
    asm("cvt.rna.tf32.f32 %0, %1;" : "=r"(o) : "f"(x));
    return __uint_as_float(o);
}

// ---------------------------------------------------------------------------
// Kernel 0: weight transform  W[oc][ic][3][3] -> Wt[tap][oc][ic] (tf32-rounded)
// ---------------------------------------------------------------------------
__global__ void wtrans_kernel(const float* __restrict__ W,
                              float* __restrict__ Wt, int OC, int IC)
{
    int idx = blockIdx.x * blockDim.x + threadIdx.x;
    if (idx >= OC * IC) return;
    int oc = idx / IC, ic = idx % IC;
    const float* src = W + ((size_t)oc * IC + ic) * 9;
#pragma unroll
    for (int t = 0; t < 9; t++)
        Wt[((size_t)t * OC + oc) * IC + ic] = tf32r(src[t]);
}

// ---------------------------------------------------------------------------
// Kernel 1: LayerNorm q -> NHWC (tf32-rounded)
// ---------------------------------------------------------------------------
__global__ void ln_q_kernel(const float* __restrict__ q_inp,
                            const float* __restrict__ g,
                            const float* __restrict__ beta,
                            float* __restrict__ out)
{
    int pix = blockIdx.x * blockDim.x + threadIdx.x;
    if (pix >= HW) return;
    int bb = blockIdx.z;

    const float* base = q_inp + ((size_t)bb * C_DIM) * HW + pix;
    float vals[C_DIM];
    float sum = 0.f;
#pragma unroll
    for (int c = 0; c < C_DIM; c++) { float v = base[(size_t)c * HW]; vals[c] = v; sum += v; }
    float mu = sum * (1.f / C_DIM);
    float var = 0.f;
#pragma unroll
    for (int c = 0; c < C_DIM; c++) { float d = vals[c] - mu; var += d * d; }
    var *= (1.f / C_DIM);
    float inv = rsqrtf(var + LN_EPS);

    float* ob = out + ((size_t)bb * HW + pix) * C_DIM;
#pragma unroll
    for (int c = 0; c < C_DIM; c++)
        vals[c] = tf32r((vals[c] - mu) * inv * g[c] + beta[c]);
#pragma unroll
    for (int c = 0; c < C_DIM; c += 4)
        *(float4*)&ob[c] = make_float4(vals[c], vals[c+1], vals[c+2], vals[c+3]);
}

// ---------------------------------------------------------------------------
// Kernel 2: flow warp + stack + LayerNorm kv -> NHWC (tf32-rounded)
// ---------------------------------------------------------------------------
__global__ void warp_ln_kv_kernel(const float* __restrict__ k_inp,
                                  const float* __restrict__ flow_f,
                                  const float* __restrict__ flow_b,
                                  const float* __restrict__ g,
                                  const float* __restrict__ beta,
                                  float* __restrict__ out)
{
    int pix = blockIdx.x * blockDim.x + threadIdx.x;
    if (pix >= HW) return;
    int f  = blockIdx.y;   // 0..2
    int bb = blockIdx.z;   // 0..1
    int y = pix >> 7, x = pix & 127;

    int src = pix;
    bool valid = true;
    if (f != 1) {
        const float* fl = (f == 0) ? flow_f : flow_b;
        float fx = fl[((size_t)bb * 2 + 0) * HW + pix];
        float fy = fl[((size_t)bb * 2 + 1) * HW + pix];
        int ix = (int)rintf((float)x + fx);
        int iy = (int)rintf((float)y + fy);
        valid = (ix >= 0) && (ix < W_IMG) && (iy >= 0) && (iy < H_IMG);
        int cx = min(max(ix, 0), W_IMG - 1);
        int cy = min(max(iy, 0), H_IMG - 1);
        src = cy * W_IMG + cx;
    }

    const float* base = k_inp + (((size_t)bb * 3 + f) * C_DIM) * HW + src;
    float vals[C_DIM];
    float sum = 0.f;
#pragma unroll
    for (int c = 0; c < C_DIM; c++) {
        float v = valid ? base[(size_t)c * HW] : 0.f;
        vals[c] = v; sum += v;
    }
    float mu = sum * (1.f / C_DIM);
    float var = 0.f;
#pragma unroll
    for (int c = 0; c < C_DIM; c++) { float d = vals[c] - mu; var += d * d; }
    var *= (1.f / C_DIM);
    float inv = rsqrtf(var + LN_EPS);

    float* ob = out + (((size_t)(bb * 3 + f)) * HW + pix) * C_DIM;
#pragma unroll
    for (int c = 0; c < C_DIM; c++)
        vals[c] = tf32r((vals[c] - mu) * inv * g[c] + beta[c]);
#pragma unroll
    for (int c = 0; c < C_DIM; c += 4)
        *(float4*)&ob[c] = make_float4(vals[c], vals[c+1], vals[c+2], vals[c+3]);
}

// ---------------------------------------------------------------------------
// Kernel 3: 3x3 conv as implicit GEMM on wmma tf32 (m16n16k8).
// One CTA = one image row (M = 128 px) x N_TILE output channels.
// A: SMEM [3 rows][130 px][68f] (pre-rounded NHWC slice with halo).
// B: SMEM per-dy [3 dx][N_TILE oc][68f] from Wt[tap][oc][ic] (pre-rounded).
// 8 warps = 2 (px) x 4 (oc); warp = 64 px x (N_TILE/4) oc.
// ---------------------------------------------------------------------------
#define AROW    68
#define A_ELEMS (3 * 130 * AROW)            // 26520 floats

template <int N_TILE, bool OUT_NHWC>
__global__ __launch_bounds__(256, 1)
void conv3x3_wmma_kernel(const float* __restrict__ in,   // NHWC (tf32 vals)
                         const float* __restrict__ Wt,   // [9][OC][IC] (tf32 vals)
                         float* __restrict__ out,
                         int IC, int OC)
{
    constexpr int NF  = N_TILE / 64;         // B fragments per warp (1 or 2)
    constexpr int OCW = N_TILE / 4;          // oc per warp

    extern __shared__ float smem[];
    float* sA = smem;                        // [3][130][AROW]
    float* sB = smem + A_ELEMS;              // [3][N_TILE][AROW]

    int tid = threadIdx.x;
    int wid = tid >> 5;

    int y   = blockIdx.x;
    int oc0 = blockIdx.y * N_TILE;
    int img = blockIdx.z;

    int warp_px = wid & 1;                   // 0..1  (64 px each)
    int warp_oc = wid >> 1;                  // 0..3

    wmma::fragment<wmma::accumulator, 16, 16, 8, float> acc[4][NF];
#pragma unroll
    for (int mf = 0; mf < 4; mf++)
#pragma unroll
        for (int nf = 0; nf < NF; nf++) wmma::fill_fragment(acc[mf][nf], 0.0f);

    const int chunks = IC / 64;

    for (int c = 0; c < chunks; c++) {
        int ic0 = c * 64;

        __syncthreads();
        // ---- stage A: 3 rows x 130 px x 64 ic (pure float4 copy) ----
        for (int i = tid; i < 3 * 130 * 16; i += 256) {
            int r   = i / (130 * 16);
            int rem = i % (130 * 16);
            int p   = rem >> 4;
            int f4  = rem & 15;
            int gy = y + r - 1, gx = p - 1;
            float4 v = make_float4(0.f, 0.f, 0.f, 0.f);
            if (gy >= 0 && gy < H_IMG && gx >= 0 && gx < W_IMG)
                v = *(const float4*)&in[(((size_t)img * H_IMG + gy) * W_IMG + gx) * IC + ic0 + f4 * 4];
            *(float4*)&sA[(r * 130 + p) * AROW + f4 * 4] = v;
        }

        for (int dy = 0; dy < 3; dy++) {
            if (dy > 0) __syncthreads();     // protect sB reuse
            // ---- stage B: taps (dy,0..2) x N_TILE oc x 64 ic ----
            for (int i = tid; i < 3 * N_TILE * 16; i += 256) {
                int dx  = i / (N_TILE * 16);
                int rem = i % (N_TILE * 16);
                int o   = rem >> 4;
                int f4  = rem & 15;
                int tap = dy * 3 + dx;
                *(float4*)&sB[(dx * N_TILE + o) * AROW + f4 * 4] =
                    *(const float4*)&Wt[(((size_t)tap * OC) + oc0 + o) * IC + ic0 + f4 * 4];
            }
            __syncthreads();

            // ---- compute ----
#pragma unroll
            for (int dx = 0; dx < 3; dx++) {
#pragma unroll
                for (int s = 0; s < 8; s++) {
                    wmma::fragment<wmma::matrix_b, 16, 16, 8,
                                   wmma::precision::tf32, wmma::col_major> bf[NF];
#pragma unroll
                    for (int nf = 0; nf < NF; nf++)
                        wmma::load_matrix_sync(
                            bf[nf],
                            &sB[(dx * N_TILE + warp_oc * OCW + nf * 16) * AROW + s * 8],
                            AROW);
#pragma unroll
                    for (int mf = 0; mf < 4; mf++) {
                        int px = warp_px * 64 + mf * 16;
                        wmma::fragment<wmma::matrix_a, 16, 16, 8,
                                       wmma::precision::tf32, wmma::row_major> af;
                        wmma::load_matrix_sync(
                            af, &sA[(dy * 130 + px + dx) * AROW + s * 8], AROW);
#pragma unroll
                        for (int nf = 0; nf < NF; nf++)
                            wmma::mma_sync(acc[mf][nf], af, bf[nf], acc[mf][nf]);
                    }
                }
            }
        }
    }

    // ---- epilogue ----
#pragma unroll
    for (int mf = 0; mf < 4; mf++) {
        int px = warp_px * 64 + mf * 16;
#pragma unroll
        for (int nf = 0; nf < NF; nf++) {
            int oc = oc0 + warp_oc * OCW + nf * 16;
            if (OUT_NHWC) {
                float* dst = &out[(((size_t)img * H_IMG + y) * W_IMG + px) * OC + oc];
                wmma::store_matrix_sync(dst, acc[mf][nf], OC, wmma::mem_row_major);
            } else {
                float* dst = &out[(((size_t)img * OC + oc) * H_IMG + y) * W_IMG + px];
                wmma::store_matrix_sync(dst, acc[mf][nf], HW, wmma::mem_col_major);
            }
        }
    }
}

// ---------------------------------------------------------------------------
// Kernel 4: windowed attention; q NHWC [b][pix][512], kv NHWC [img][pix][1024]
// (k = ch 0..511, v = ch 512..1023); out NHWC [b][pix][512] (tf32-rounded).
// ---------------------------------------------------------------------------
__global__ void attn_kernel(const float* __restrict__ q,
                            const float* __restrict__ kv,
                            const float* __restrict__ stat,
                            float* __restrict__ outp)
{
    int win = blockIdx.x;         // 0..1023
    int hh  = blockIdx.y;         // 0..7
    int bb  = blockIdx.z;         // 0..1
    int wy = win >> 5, wx = win & 31;

    __shared__ float sq[Q_L][DIM_HEAD + 1];
    __shared__ float sk[KV_L][DIM_HEAD + 1];
    __shared__ float sv[KV_L][DIM_HEAD + 1];
    __shared__ float ssim[Q_L][KV_L + 1];

    int tid = threadIdx.x;        // 0..127

    // load q: 16 px x 16 float4 (coalesced)
    for (int i = tid; i < Q_L * 16; i += 128) {
        int pi = i >> 4, c = i & 15;
        int py = pi >> 2, px = pi & 3;
        int pix = (wy * 4 + py) * W_IMG + wx * 4 + px;
        float4 v = *(const float4*)&q[((size_t)bb * HW + pix) * INNER + hh * DIM_HEAD + c * 4];
        sq[pi][c*4+0] = v.x * 0.125f; sq[pi][c*4+1] = v.y * 0.125f;
        sq[pi][c*4+2] = v.z * 0.125f; sq[pi][c*4+3] = v.w * 0.125f;
    }
    // load k, v: 48 px x 16 float4 each (coalesced)
    for (int i = tid; i < KV_L * 16; i += 128) {
        int j = i >> 4, c = i & 15;
        int f = j >> 4, pi = j & 15;
        int py = pi >> 2, px = pi & 3;
        int pix = (wy * 4 + py) * W_IMG + wx * 4 + px;
        size_t base = ((size_t)(bb * 3 + f) * HW + pix) * (2 * INNER) + hh * DIM_HEAD + c * 4;
        float4 kk = *(const float4*)&kv[base];
        float4 vv = *(const float4*)&kv[base + INNER];
        sk[j][c*4+0] = kk.x; sk[j][c*4+1] = kk.y; sk[j][c*4+2] = kk.z; sk[j][c*4+3] = kk.w;
        sv[j][c*4+0] = vv.x; sv[j][c*4+1] = vv.y; sv[j][c*4+2] = vv.z; sv[j][c*4+3] = vv.w;
    }
    __syncthreads();

    for (int e = tid; e < Q_L * KV_L; e += 128) {
        int i = e / KV_L, j = e % KV_L;
        float s = 0.f;
#pragma unroll
        for (int d = 0; d < DIM_HEAD; d++) s += sq[i][d] * sk[j][d];
        ssim[i][j] = s + stat[((size_t)hh * Q_L + i) * KV_L + j];
    }
    __syncthreads();

    if (tid < Q_L) {
        float m = -1e30f;
        for (int j = 0; j < KV_L; j++) m = fmaxf(m, ssim[tid][j]);
        float ssum = 0.f;
        for (int j = 0; j < KV_L; j++) {
            float e = expf(ssim[tid][j] - m);
            ssim[tid][j] = e; ssum += e;
        }
        float inv = 1.f / ssum;
        for (int j = 0; j < KV_L; j++) ssim[tid][j] *= inv;
    }
    __syncthreads();

    for (int e = tid; e < Q_L * Q_L; e += 128) {   // 16 px x 16 float4
        int pi = e >> 4, c = e & 15;
        float4 r;
        float* rp = (float*)&r;
#pragma unroll
        for (int t = 0; t < 4; t++) {
            int d = c * 4 + t;
            float s = 0.f;
#pragma unroll
            for (int j = 0; j < KV_L; j++) s += ssim[pi][j] * sv[j][d];
            rp[t] = tf32r(s);
        }
        int py = pi >> 2, px = pi & 3;
        int pix = (wy * 4 + py) * W_IMG + wx * 4 + px;
        *(float4*)&outp[((size_t)bb * HW + pix) * INNER + hh * DIM_HEAD + c * 4] = r;
    }
}

// ---------------------------------------------------------------------------
// Host launch
// ---------------------------------------------------------------------------
extern "C" void kernel_launch(void* const* d_in, const int* in_sizes, int n_in,
                              void* d_out, int out_size)
{
    (void)in_sizes; (void)n_in; (void)out_size;

    const float* q_inp   = (const float*)d_in[0];
    const float* k_inp   = (const float*)d_in[1];
    const float* flow_f  = (const float*)d_in[2];
    const float* flow_b  = (const float*)d_in[3];
    const float* gq      = (const float*)d_in[4];
    const float* bq      = (const float*)d_in[5];
    const float* gkv     = (const float*)d_in[6];
    const float* bkv     = (const float*)d_in[7];
    const float* Wq      = (const float*)d_in[8];
    const float* Wkv     = (const float*)d_in[9];
    const float* Wout    = (const float*)d_in[10];
    const float* statica = (const float*)d_in[11];

    float *qn, *kvn, *qb, *kvb, *attb, *wtq, *wtkv, *wtout;
    cudaGetSymbolAddress((void**)&qn,    g_qn);
    cudaGetSymbolAddress((void**)&kvn,   g_kvn);
    cudaGetSymbolAddress((void**)&qb,    g_q);
    cudaGetSymbolAddress((void**)&kvb,   g_kv);
    cudaGetSymbolAddress((void**)&attb,  g_att);
    cudaGetSymbolAddress((void**)&wtq,   g_wt_q);
    cudaGetSymbolAddress((void**)&wtkv,  g_wt_kv);
    cudaGetSymbolAddress((void**)&wtout, g_wt_out);

    const int SMEM128 = (A_ELEMS + 3 * 128 * AROW) * 4;   // 210528
    const int SMEM64  = (A_ELEMS + 3 * 64  * AROW) * 4;   // 158304
    cudaFuncSetAttribute((const void*)conv3x3_wmma_kernel<128, true>,
                         cudaFuncAttributeMaxDynamicSharedMemorySize, SMEM128);
    cudaFuncSetAttribute((const void*)conv3x3_wmma_kernel<64, false>,
                         cudaFuncAttributeMaxDynamicSharedMemorySize, SMEM64);

    // 0) weight transforms (tf32-rounded)
    wtrans_kernel<<<(INNER * C_DIM + 255) / 256, 256>>>(Wq, wtq, INNER, C_DIM);
    wtrans_kernel<<<(2 * INNER * C_DIM + 255) / 256, 256>>>(Wkv, wtkv, 2 * INNER, C_DIM);
    wtrans_kernel<<<(C_DIM * INNER + 255) / 256, 256>>>(Wout, wtout, C_DIM, INNER);

    // 1) layernorm q  (NHWC out)
    ln_q_kernel<<<dim3(HW / 256, 1, B), 256>>>(q_inp, gq, bq, qn);

    // 2) warp + stack + layernorm kv  (NHWC out)
    warp_ln_kv_kernel<<<dim3(HW / 256, 3, B), 256>>>(k_inp, flow_f, flow_b, gkv, bkv, kvn);

    // 3) conv q: 64 -> 512, NHWC out
    conv3x3_wmma_kernel<128, true><<<dim3(H_IMG, INNER / 128, B), 256, SMEM128>>>(
        qn, wtq, qb, C_DIM, INNER);

    // 4) conv kv: 64 -> 1024, NHWC out
    conv3x3_wmma_kernel<128, true><<<dim3(H_IMG, (2 * INNER) / 128, B * 3), 256, SMEM128>>>(
        kvn, wtkv, kvb, C_DIM, 2 * INNER);

    // 5) attention (all NHWC)
    attn_kernel<<<dim3(1024, HEADS, B), 128>>>(qb, kvb, statica, attb);

    // 6) conv out: 512 -> 64, NCHW out -> d_out
    conv3x3_wmma_kernel<64, false><<<dim3(H_IMG, 1, B), 256, SMEM64>>>(
        attb, wtout, (float*)d_out, INNER, C_DIM);
}

// round 6
// speedup vs baseline: 5.1467x; 2.5741x over previous
#include <cuda_runtime.h>
#include <cuda_fp16.h>
#include <mma.h>
#include <math.h>
#include <stdint.h>

using namespace nvcuda;

// ---------------------------------------------------------------------------
// Problem constants
// ---------------------------------------------------------------------------
#define B       2
#define C_DIM   64
#define H_IMG   128
#define W_IMG   128
#define HW      (H_IMG * W_IMG)          // 16384
#define HEADS   8
#define DIM_HEAD 64
#define INNER   (HEADS * DIM_HEAD)       // 512
#define Q_L     16
#define KV_L    48
#define LN_EPS  1e-5f

// ---------------------------------------------------------------------------
// Scratch buffers (__device__ globals; allocation is forbidden)
// conv inputs fp16 NHWC; conv q/kv outputs fp32 NHWC; final d_out fp32 NCHW.
// ---------------------------------------------------------------------------
__device__ __half g_qn  [B * HW * C_DIM];            // LN(q), NHWC fp16
__device__ __half g_kvn [B * 3 * HW * C_DIM];        // warped+LN kv, NHWC fp16
__device__ float  g_q   [B * HW * INNER];            // conv q out, NHWC fp32
__device__ float  g_kv  [B * 3 * HW * 2 * INNER];    // conv kv out, NHWC fp32
__device__ __half g_att [B * HW * INNER];            // attention out, NHWC fp16
__device__ __half g_wt_q  [9 * INNER * C_DIM];       // Wq  as [tap][oc][ic] fp16
__device__ __half g_wt_kv [9 * 2 * INNER * C_DIM];   // Wkv as [tap][oc][ic] fp16
__device__ __half g_wt_out[9 * C_DIM * INNER];       // Wout as [tap][oc][ic] fp16

// ---------------------------------------------------------------------------
// Kernel 0: weight transform  W[oc][ic][3][3] -> Wt[tap][oc][ic] (fp16)
// ---------------------------------------------------------------------------
__global__ void wtrans_kernel(const float* __restrict__ W,
                              __half* __restrict__ Wt, int OC, int IC)
{
    int idx = blockIdx.x * blockDim.x + threadIdx.x;
    if (idx >= OC * IC) return;
    int oc = idx / IC, ic = idx % IC;
    const float* src = W + ((size_t)oc * IC + ic) * 9;
#pragma unroll
    for (int t = 0; t < 9; t++)
        Wt[((size_t)t * OC + oc) * IC + ic] = __float2half_rn(src[t]);
}

// ---------------------------------------------------------------------------
// Kernel 1: LayerNorm q -> NHWC fp16
// ---------------------------------------------------------------------------
__global__ void ln_q_kernel(const float* __restrict__ q_inp,
                            const float* __restrict__ g,
                            const float* __restrict__ beta,
                            __half* __restrict__ out)
{
    int pix = blockIdx.x * blockDim.x + threadIdx.x;
    if (pix >= HW) return;
    int bb = blockIdx.z;

    const float* base = q_inp + ((size_t)bb * C_DIM) * HW + pix;
    float vals[C_DIM];
    float sum = 0.f;
#pragma unroll
    for (int c = 0; c < C_DIM; c++) { float v = base[(size_t)c * HW]; vals[c] = v; sum += v; }
    float mu = sum * (1.f / C_DIM);
    float var = 0.f;
#pragma unroll
    for (int c = 0; c < C_DIM; c++) { float d = vals[c] - mu; var += d * d; }
    var *= (1.f / C_DIM);
    float inv = rsqrtf(var + LN_EPS);

    __half2* ob = (__half2*)(out + ((size_t)bb * HW + pix) * C_DIM);
#pragma unroll
    for (int c = 0; c < C_DIM; c += 2)
        ob[c >> 1] = __floats2half2_rn((vals[c]   - mu) * inv * g[c]   + beta[c],
                                       (vals[c+1] - mu) * inv * g[c+1] + beta[c+1]);
}

// ---------------------------------------------------------------------------
// Kernel 2: flow warp + stack + LayerNorm kv -> NHWC fp16
// ---------------------------------------------------------------------------
__global__ void warp_ln_kv_kernel(const float* __restrict__ k_inp,
                                  const float* __restrict__ flow_f,
                                  const float* __restrict__ flow_b,
                                  const float* __restrict__ g,
                                  const float* __restrict__ beta,
                                  __half* __restrict__ out)
{
    int pix = blockIdx.x * blockDim.x + threadIdx.x;
    if (pix >= HW) return;
    int f  = blockIdx.y;   // 0..2
    int bb = blockIdx.z;   // 0..1
    int y = pix >> 7, x = pix & 127;

    int src = pix;
    bool valid = true;
    if (f != 1) {
        const float* fl = (f == 0) ? flow_f : flow_b;
        float fx = fl[((size_t)bb * 2 + 0) * HW + pix];
        float fy = fl[((size_t)bb * 2 + 1) * HW + pix];
        int ix = (int)rintf((float)x + fx);
        int iy = (int)rintf((float)y + fy);
        valid = (ix >= 0) && (ix < W_IMG) && (iy >= 0) && (iy < H_IMG);
        int cx = min(max(ix, 0), W_IMG - 1);
        int cy = min(max(iy, 0), H_IMG - 1);
        src = cy * W_IMG + cx;
    }

    const float* base = k_inp + (((size_t)bb * 3 + f) * C_DIM) * HW + src;
    float vals[C_DIM];
    float sum = 0.f;
#pragma unroll
    for (int c = 0; c < C_DIM; c++) {
        float v = valid ? base[(size_t)c * HW] : 0.f;
        vals[c] = v; sum += v;
    }
    float mu = sum * (1.f / C_DIM);
    float var = 0.f;
#pragma unroll
    for (int c = 0; c < C_DIM; c++) { float d = vals[c] - mu; var += d * d; }
    var *= (1.f / C_DIM);
    float inv = rsqrtf(var + LN_EPS);

    __half2* ob = (__half2*)(out + (((size_t)(bb * 3 + f)) * HW + pix) * C_DIM);
#pragma unroll
    for (int c = 0; c < C_DIM; c += 2)
        ob[c >> 1] = __floats2half2_rn((vals[c]   - mu) * inv * g[c]   + beta[c],
                                       (vals[c+1] - mu) * inv * g[c+1] + beta[c+1]);
}

// ---------------------------------------------------------------------------
// Kernel 3: 3x3 conv as implicit GEMM on wmma fp16 (m16n16k16, fp32 accum).
// One CTA = TWO image rows (M = 256 px) x N_TILE output channels.
// A: SMEM [4 rows][130 px][72 halfs] (NHWC slice with halo).
// B: SMEM per-dy [3 dx][N_TILE oc][72 halfs] from Wt[tap][oc][ic].
// 8 warps = 2 rows x 2 px-halves x 2 oc-halves; warp = 64 px x N_TILE/2 oc.
// ---------------------------------------------------------------------------
#define AROWH    72                         // halfs per px (64 + 8 pad)
#define A_ELEMSH (4 * 130 * AROWH)          // 37440 halfs

template <int N_TILE, bool OUT_NHWC>
__global__ __launch_bounds__(256, 1)
void conv3x3_h_kernel(const __half* __restrict__ in,   // NHWC fp16
                      const __half* __restrict__ Wt,   // [9][OC][IC] fp16
                      float* __restrict__ out,
                      int IC, int OC)
{
    constexpr int OCW = N_TILE / 2;          // oc per warp
    constexpr int NF  = OCW / 16;            // B fragments per warp

    extern __shared__ __half smh[];
    __half* sA = smh;                        // [4][130][AROWH]
    __half* sB = smh + A_ELEMSH;             // [3][N_TILE][AROWH]

    int tid = threadIdx.x;
    int wid = tid >> 5;

    int y0  = blockIdx.x * 2;
    int oc0 = blockIdx.y * N_TILE;
    int img = blockIdx.z;

    int warp_row = wid & 1;                  // output row within strip
    int warp_pxh = (wid >> 1) & 1;           // 0..1 (64 px each)
    int warp_ocg = wid >> 2;                 // 0..1

    wmma::fragment<wmma::accumulator, 16, 16, 16, float> acc[4][NF];
#pragma unroll
    for (int mf = 0; mf < 4; mf++)
#pragma unroll
        for (int nf = 0; nf < NF; nf++) wmma::fill_fragment(acc[mf][nf], 0.0f);

    const int chunks = IC / 64;

    for (int c = 0; c < chunks; c++) {
        int ic0 = c * 64;

        __syncthreads();
        // ---- stage A: 4 rows x 130 px x 64 ic (16B vector copies) ----
        for (int i = tid; i < 4 * 130 * 8; i += 256) {
            int r   = i / (130 * 8);
            int rem = i % (130 * 8);
            int p   = rem >> 3;
            int v   = rem & 7;
            int gy = y0 + r - 1, gx = p - 1;
            uint4 d = make_uint4(0u, 0u, 0u, 0u);
            if (gy >= 0 && gy < H_IMG && gx >= 0 && gx < W_IMG)
                d = *(const uint4*)&in[(((size_t)img * H_IMG + gy) * W_IMG + gx) * IC + ic0 + v * 8];
            *(uint4*)&sA[(r * 130 + p) * AROWH + v * 8] = d;
        }

        for (int dy = 0; dy < 3; dy++) {
            if (dy > 0) __syncthreads();     // protect sB reuse
            // ---- stage B: taps (dy,0..2) x N_TILE oc x 64 ic ----
            for (int i = tid; i < 3 * N_TILE * 8; i += 256) {
                int dx  = i / (N_TILE * 8);
                int rem = i % (N_TILE * 8);
                int o   = rem >> 3;
                int v   = rem & 7;
                int tap = dy * 3 + dx;
                *(uint4*)&sB[(dx * N_TILE + o) * AROWH + v * 8] =
                    *(const uint4*)&Wt[(((size_t)tap * OC) + oc0 + o) * IC + ic0 + v * 8];
            }
            __syncthreads();

            // ---- compute ----
#pragma unroll
            for (int dx = 0; dx < 3; dx++) {
#pragma unroll
                for (int s = 0; s < 4; s++) {
                    wmma::fragment<wmma::matrix_b, 16, 16, 16, __half,
                                   wmma::col_major> bf[NF];
#pragma unroll
                    for (int nf = 0; nf < NF; nf++)
                        wmma::load_matrix_sync(
                            bf[nf],
                            &sB[(dx * N_TILE + warp_ocg * OCW + nf * 16) * AROWH + s * 16],
                            AROWH);
#pragma unroll
                    for (int mf = 0; mf < 4; mf++) {
                        int px = warp_pxh * 64 + mf * 16;
                        wmma::fragment<wmma::matrix_a, 16, 16, 16, __half,
                                       wmma::row_major> af;
                        wmma::load_matrix_sync(
                            af,
                            &sA[((warp_row + dy) * 130 + px + dx) * AROWH + s * 16],
                            AROWH);
#pragma unroll
                        for (int nf = 0; nf < NF; nf++)
                            wmma::mma_sync(acc[mf][nf], af, bf[nf], acc[mf][nf]);
                    }
                }
            }
        }
    }

    // ---- epilogue (fp32 out) ----
    int y = y0 + warp_row;
#pragma unroll
    for (int mf = 0; mf < 4; mf++) {
        int px = warp_pxh * 64 + mf * 16;
#pragma unroll
        for (int nf = 0; nf < NF; nf++) {
            int oc = oc0 + warp_ocg * OCW + nf * 16;
            if (OUT_NHWC) {
                float* dst = &out[(((size_t)img * H_IMG + y) * W_IMG + px) * OC + oc];
                wmma::store_matrix_sync(dst, acc[mf][nf], OC, wmma::mem_row_major);
            } else {
                float* dst = &out[(((size_t)img * OC + oc) * H_IMG + y) * W_IMG + px];
                wmma::store_matrix_sync(dst, acc[mf][nf], HW, wmma::mem_col_major);
            }
        }
    }
}

// ---------------------------------------------------------------------------
// Kernel 4: windowed attention; q/kv fp32 NHWC in, out fp16 NHWC.
// ---------------------------------------------------------------------------
__global__ void attn_kernel(const float* __restrict__ q,
                            const float* __restrict__ kv,
                            const float* __restrict__ stat,
                            __half* __restrict__ outp)
{
    int win = blockIdx.x;         // 0..1023
    int hh  = blockIdx.y;         // 0..7
    int bb  = blockIdx.z;         // 0..1
    int wy = win >> 5, wx = win & 31;

    __shared__ float sq[Q_L][DIM_HEAD + 1];
    __shared__ float sk[KV_L][DIM_HEAD + 1];
    __shared__ float sv[KV_L][DIM_HEAD + 1];
    __shared__ float ssim[Q_L][KV_L + 1];

    int tid = threadIdx.x;        // 0..127

    for (int i = tid; i < Q_L * 16; i += 128) {
        int pi = i >> 4, c = i & 15;
        int py = pi >> 2, px = pi & 3;
        int pix = (wy * 4 + py) * W_IMG + wx * 4 + px;
        float4 v = *(const float4*)&q[((size_t)bb * HW + pix) * INNER + hh * DIM_HEAD + c * 4];
        sq[pi][c*4+0] = v.x * 0.125f; sq[pi][c*4+1] = v.y * 0.125f;
        sq[pi][c*4+2] = v.z * 0.125f; sq[pi][c*4+3] = v.w * 0.125f;
    }
    for (int i = tid; i < KV_L * 16; i += 128) {
        int j = i >> 4, c = i & 15;
        int f = j >> 4, pi = j & 15;
        int py = pi >> 2, px = pi & 3;
        int pix = (wy * 4 + py) * W_IMG + wx * 4 + px;
        size_t base = ((size_t)(bb * 3 + f) * HW + pix) * (2 * INNER) + hh * DIM_HEAD + c * 4;
        float4 kk = *(const float4*)&kv[base];
        float4 vv = *(const float4*)&kv[base + INNER];
        sk[j][c*4+0] = kk.x; sk[j][c*4+1] = kk.y; sk[j][c*4+2] = kk.z; sk[j][c*4+3] = kk.w;
        sv[j][c*4+0] = vv.x; sv[j][c*4+1] = vv.y; sv[j][c*4+2] = vv.z; sv[j][c*4+3] = vv.w;
    }
    __syncthreads();

    for (int e = tid; e < Q_L * KV_L; e += 128) {
        int i = e / KV_L, j = e % KV_L;
        float s = 0.f;
#pragma unroll
        for (int d = 0; d < DIM_HEAD; d++) s += sq[i][d] * sk[j][d];
        ssim[i][j] = s + stat[((size_t)hh * Q_L + i) * KV_L + j];
    }
    __syncthreads();

    if (tid < Q_L) {
        float m = -1e30f;
        for (int j = 0; j < KV_L; j++) m = fmaxf(m, ssim[tid][j]);
        float ssum = 0.f;
        for (int j = 0; j < KV_L; j++) {
            float e = expf(ssim[tid][j] - m);
            ssim[tid][j] = e; ssum += e;
        }
        float inv = 1.f / ssum;
        for (int j = 0; j < KV_L; j++) ssim[tid][j] *= inv;
    }
    __syncthreads();

    for (int e = tid; e < Q_L * Q_L; e += 128) {   // 16 px x 16 4-channel groups
        int pi = e >> 4, c = e & 15;
        float r[4];
#pragma unroll
        for (int t = 0; t < 4; t++) {
            int d = c * 4 + t;
            float s = 0.f;
#pragma unroll
            for (int j = 0; j < KV_L; j++) s += ssim[pi][j] * sv[j][d];
            r[t] = s;
        }
        int py = pi >> 2, px = pi & 3;
        int pix = (wy * 4 + py) * W_IMG + wx * 4 + px;
        __half2* op = (__half2*)&outp[((size_t)bb * HW + pix) * INNER + hh * DIM_HEAD + c * 4];
        op[0] = __floats2half2_rn(r[0], r[1]);
        op[1] = __floats2half2_rn(r[2], r[3]);
    }
}

// ---------------------------------------------------------------------------
// Host launch
// ---------------------------------------------------------------------------
extern "C" void kernel_launch(void* const* d_in, const int* in_sizes, int n_in,
                              void* d_out, int out_size)
{
    (void)in_sizes; (void)n_in; (void)out_size;

    const float* q_inp   = (const float*)d_in[0];
    const float* k_inp   = (const float*)d_in[1];
    const float* flow_f  = (const float*)d_in[2];
    const float* flow_b  = (const float*)d_in[3];
    const float* gq      = (const float*)d_in[4];
    const float* bq      = (const float*)d_in[5];
    const float* gkv     = (const float*)d_in[6];
    const float* bkv     = (const float*)d_in[7];
    const float* Wq      = (const float*)d_in[8];
    const float* Wkv     = (const float*)d_in[9];
    const float* Wout    = (const float*)d_in[10];
    const float* statica = (const float*)d_in[11];

    __half *qn, *kvn, *attb, *wtq, *wtkv, *wtout;
    float  *qb, *kvb;
    cudaGetSymbolAddress((void**)&qn,    g_qn);
    cudaGetSymbolAddress((void**)&kvn,   g_kvn);
    cudaGetSymbolAddress((void**)&qb,    g_q);
    cudaGetSymbolAddress((void**)&kvb,   g_kv);
    cudaGetSymbolAddress((void**)&attb,  g_att);
    cudaGetSymbolAddress((void**)&wtq,   g_wt_q);
    cudaGetSymbolAddress((void**)&wtkv,  g_wt_kv);
    cudaGetSymbolAddress((void**)&wtout, g_wt_out);

    const int SMEM128 = (A_ELEMSH + 3 * 128 * AROWH) * 2;   // 130,176 B
    const int SMEM64  = (A_ELEMSH + 3 * 64  * AROWH) * 2;   // 102,528 B
    cudaFuncSetAttribute((const void*)conv3x3_h_kernel<128, true>,
                         cudaFuncAttributeMaxDynamicSharedMemorySize, SMEM128);
    cudaFuncSetAttribute((const void*)conv3x3_h_kernel<64, false>,
                         cudaFuncAttributeMaxDynamicSharedMemorySize, SMEM64);

    // 0) weight transforms (fp16)
    wtrans_kernel<<<(INNER * C_DIM + 255) / 256, 256>>>(Wq, wtq, INNER, C_DIM);
    wtrans_kernel<<<(2 * INNER * C_DIM + 255) / 256, 256>>>(Wkv, wtkv, 2 * INNER, C_DIM);
    wtrans_kernel<<<(C_DIM * INNER + 255) / 256, 256>>>(Wout, wtout, C_DIM, INNER);

    // 1) layernorm q  (NHWC fp16)
    ln_q_kernel<<<dim3(HW / 256, 1, B), 256>>>(q_inp, gq, bq, qn);

    // 2) warp + stack + layernorm kv  (NHWC fp16)
    warp_ln_kv_kernel<<<dim3(HW / 256, 3, B), 256>>>(k_inp, flow_f, flow_b, gkv, bkv, kvn);

    // 3) conv q: 64 -> 512, NHWC fp32 out
    conv3x3_h_kernel<128, true><<<dim3(H_IMG / 2, INNER / 128, B), 256, SMEM128>>>(
        qn, wtq, qb, C_DIM, INNER);

    // 4) conv kv: 64 -> 1024, NHWC fp32 out
    conv3x3_h_kernel<128, true><<<dim3(H_IMG / 2, (2 * INNER) / 128, B * 3), 256, SMEM128>>>(
        kvn, wtkv, kvb, C_DIM, 2 * INNER);

    // 5) attention (fp32 in, fp16 NHWC out)
    attn_kernel<<<dim3(1024, HEADS, B), 128>>>(qb, kvb, statica, attb);

    // 6) conv out: 512 -> 64, fp32 NCHW out -> d_out
    conv3x3_h_kernel<64, false><<<dim3(H_IMG / 2, 1, B), 256, SMEM64>>>(
        attb, wtout, (float*)d_out, INNER, C_DIM);
}

// round 7
// speedup vs baseline: 5.5640x; 1.0811x over previous
#include <cuda_runtime.h>
#include <cuda_fp16.h>
#include <mma.h>
#include <math.h>
#include <stdint.h>

using namespace nvcuda;

// ---------------------------------------------------------------------------
// Problem constants
// ---------------------------------------------------------------------------
#define B       2
#define C_DIM   64
#define H_IMG   128
#define W_IMG   128
#define HW      (H_IMG * W_IMG)          // 16384
#define HEADS   8
#define DIM_HEAD 64
#define INNER   (HEADS * DIM_HEAD)       // 512
#define Q_L     16
#define KV_L    48
#define LN_EPS  1e-5f

// ---------------------------------------------------------------------------
// Scratch buffers (__device__ globals; allocation is forbidden)
// conv inputs fp16 NHWC; conv q/kv outputs fp16 NHWC; final d_out fp32 NCHW.
// ---------------------------------------------------------------------------
__device__ __half g_qn  [B * HW * C_DIM];            // LN(q), NHWC fp16
__device__ __half g_kvn [B * 3 * HW * C_DIM];        // warped+LN kv, NHWC fp16
__device__ __half g_q   [B * HW * INNER];            // conv q out, NHWC fp16
__device__ __half g_kv  [B * 3 * HW * 2 * INNER];    // conv kv out, NHWC fp16
__device__ __half g_att [B * HW * INNER];            // attention out, NHWC fp16
__device__ __half g_wt_q  [9 * INNER * C_DIM];       // Wq  as [tap][oc][ic] fp16
__device__ __half g_wt_kv [9 * 2 * INNER * C_DIM];   // Wkv as [tap][oc][ic] fp16
__device__ __half g_wt_out[9 * C_DIM * INNER];       // Wout as [tap][oc][ic] fp16

// ---------------------------------------------------------------------------
// Kernel 0: weight transform  W[oc][ic][3][3] -> Wt[tap][oc][ic] (fp16)
// ---------------------------------------------------------------------------
__global__ void wtrans_kernel(const float* __restrict__ W,
                              __half* __restrict__ Wt, int OC, int IC)
{
    int idx = blockIdx.x * blockDim.x + threadIdx.x;
    if (idx >= OC * IC) return;
    int oc = idx / IC, ic = idx % IC;
    const float* src = W + ((size_t)oc * IC + ic) * 9;
#pragma unroll
    for (int t = 0; t < 9; t++)
        Wt[((size_t)t * OC + oc) * IC + ic] = __float2half_rn(src[t]);
}

// ---------------------------------------------------------------------------
// Kernel 1: LayerNorm q -> NHWC fp16
// ---------------------------------------------------------------------------
__global__ void ln_q_kernel(const float* __restrict__ q_inp,
                            const float* __restrict__ g,
                            const float* __restrict__ beta,
                            __half* __restrict__ out)
{
    int pix = blockIdx.x * blockDim.x + threadIdx.x;
    if (pix >= HW) return;
    int bb = blockIdx.z;

    const float* base = q_inp + ((size_t)bb * C_DIM) * HW + pix;
    float vals[C_DIM];
    float sum = 0.f;
#pragma unroll
    for (int c = 0; c < C_DIM; c++) { float v = base[(size_t)c * HW]; vals[c] = v; sum += v; }
    float mu = sum * (1.f / C_DIM);
    float var = 0.f;
#pragma unroll
    for (int c = 0; c < C_DIM; c++) { float d = vals[c] - mu; var += d * d; }
    var *= (1.f / C_DIM);
    float inv = rsqrtf(var + LN_EPS);

    __half2* ob = (__half2*)(out + ((size_t)bb * HW + pix) * C_DIM);
#pragma unroll
    for (int c = 0; c < C_DIM; c += 2)
        ob[c >> 1] = __floats2half2_rn((vals[c]   - mu) * inv * g[c]   + beta[c],
                                       (vals[c+1] - mu) * inv * g[c+1] + beta[c+1]);
}

// ---------------------------------------------------------------------------
// Kernel 2: flow warp + stack + LayerNorm kv -> NHWC fp16
// ---------------------------------------------------------------------------
__global__ void warp_ln_kv_kernel(const float* __restrict__ k_inp,
                                  const float* __restrict__ flow_f,
                                  const float* __restrict__ flow_b,
                                  const float* __restrict__ g,
                                  const float* __restrict__ beta,
                                  __half* __restrict__ out)
{
    int pix = blockIdx.x * blockDim.x + threadIdx.x;
    if (pix >= HW) return;
    int f  = blockIdx.y;   // 0..2
    int bb = blockIdx.z;   // 0..1
    int y = pix >> 7, x = pix & 127;

    int src = pix;
    bool valid = true;
    if (f != 1) {
        const float* fl = (f == 0) ? flow_f : flow_b;
        float fx = fl[((size_t)bb * 2 + 0) * HW + pix];
        float fy = fl[((size_t)bb * 2 + 1) * HW + pix];
        int ix = (int)rintf((float)x + fx);
        int iy = (int)rintf((float)y + fy);
        valid = (ix >= 0) && (ix < W_IMG) && (iy >= 0) && (iy < H_IMG);
        int cx = min(max(ix, 0), W_IMG - 1);
        int cy = min(max(iy, 0), H_IMG - 1);
        src = cy * W_IMG + cx;
    }

    const float* base = k_inp + (((size_t)bb * 3 + f) * C_DIM) * HW + src;
    float vals[C_DIM];
    float sum = 0.f;
#pragma unroll
    for (int c = 0; c < C_DIM; c++) {
        float v = valid ? base[(size_t)c * HW] : 0.f;
        vals[c] = v; sum += v;
    }
    float mu = sum * (1.f / C_DIM);
    float var = 0.f;
#pragma unroll
    for (int c = 0; c < C_DIM; c++) { float d = vals[c] - mu; var += d * d; }
    var *= (1.f / C_DIM);
    float inv = rsqrtf(var + LN_EPS);

    __half2* ob = (__half2*)(out + (((size_t)(bb * 3 + f)) * HW + pix) * C_DIM);
#pragma unroll
    for (int c = 0; c < C_DIM; c += 2)
        ob[c >> 1] = __floats2half2_rn((vals[c]   - mu) * inv * g[c]   + beta[c],
                                       (vals[c+1] - mu) * inv * g[c+1] + beta[c+1]);
}

// ---------------------------------------------------------------------------
// Kernel 3: 3x3 conv as implicit GEMM on wmma fp16 (m16n16k16, fp32 accum).
// One CTA = TWO image rows (M = 256 px) x N_TILE output channels.
// A: SMEM [4 rows][130 px][72 halfs]; B per-dy: [3 dx][N_TILE oc][72 halfs].
// 8 warps = 2 rows x 2 px-halves x 2 oc-groups; warp = 64 px x (N_TILE/2) oc.
// Per K-step: 4 A-frag loads + NF B-frag loads -> 4*NF mma.
// ---------------------------------------------------------------------------
#define AROWH    72                         // halfs per px (64 + 8 pad)
#define A_ELEMSH (4 * 130 * AROWH)          // 37440 halfs

template <int N_TILE, bool OUT_FP16_NHWC>
__global__ __launch_bounds__(256, 1)
void conv3x3_h_kernel(const __half* __restrict__ in,   // NHWC fp16
                      const __half* __restrict__ Wt,   // [9][OC][IC] fp16
                      void* __restrict__ out_raw,
                      int IC, int OC)
{
    constexpr int OCW = N_TILE / 2;          // oc per warp (64 or 32)
    constexpr int NF  = OCW / 16;            // B fragments per warp (4 or 2)

    extern __shared__ __half smh[];
    __half* sA = smh;                        // [4][130][AROWH]
    __half* sB = smh + A_ELEMSH;             // [3][N_TILE][AROWH]

    int tid = threadIdx.x;
    int wid = tid >> 5;
    int lane = tid & 31;

    int y0  = blockIdx.x * 2;
    int oc0 = blockIdx.y * N_TILE;
    int img = blockIdx.z;

    int warp_row = wid & 1;                  // output row within strip
    int warp_pxh = (wid >> 1) & 1;           // 0..1 (64 px each)
    int warp_ocg = wid >> 2;                 // 0..1

    wmma::fragment<wmma::accumulator, 16, 16, 16, float> acc[4][NF];
#pragma unroll
    for (int mf = 0; mf < 4; mf++)
#pragma unroll
        for (int nf = 0; nf < NF; nf++) wmma::fill_fragment(acc[mf][nf], 0.0f);

    const int chunks = IC / 64;

    for (int c = 0; c < chunks; c++) {
        int ic0 = c * 64;

        __syncthreads();
        // ---- stage A: 4 rows x 130 px x 64 ic (16B vector copies) ----
        for (int i = tid; i < 4 * 130 * 8; i += 256) {
            int r   = i / (130 * 8);
            int rem = i % (130 * 8);
            int p   = rem >> 3;
            int v   = rem & 7;
            int gy = y0 + r - 1, gx = p - 1;
            uint4 d = make_uint4(0u, 0u, 0u, 0u);
            if (gy >= 0 && gy < H_IMG && gx >= 0 && gx < W_IMG)
                d = *(const uint4*)&in[(((size_t)img * H_IMG + gy) * W_IMG + gx) * IC + ic0 + v * 8];
            *(uint4*)&sA[(r * 130 + p) * AROWH + v * 8] = d;
        }

        for (int dy = 0; dy < 3; dy++) {
            if (dy > 0) __syncthreads();     // protect sB reuse
            // ---- stage B: taps (dy,0..2) x N_TILE oc x 64 ic ----
            for (int i = tid; i < 3 * N_TILE * 8; i += 256) {
                int dx  = i / (N_TILE * 8);
                int rem = i % (N_TILE * 8);
                int o   = rem >> 3;
                int v   = rem & 7;
                int tap = dy * 3 + dx;
                *(uint4*)&sB[(dx * N_TILE + o) * AROWH + v * 8] =
                    *(const uint4*)&Wt[(((size_t)tap * OC) + oc0 + o) * IC + ic0 + v * 8];
            }
            __syncthreads();

            // ---- compute ----
#pragma unroll
            for (int dx = 0; dx < 3; dx++) {
#pragma unroll
                for (int s = 0; s < 4; s++) {
                    wmma::fragment<wmma::matrix_b, 16, 16, 16, __half,
                                   wmma::col_major> bf[NF];
#pragma unroll
                    for (int nf = 0; nf < NF; nf++)
                        wmma::load_matrix_sync(
                            bf[nf],
                            &sB[(dx * N_TILE + warp_ocg * OCW + nf * 16) * AROWH + s * 16],
                            AROWH);
#pragma unroll
                    for (int mf = 0; mf < 4; mf++) {
                        int px = warp_pxh * 64 + mf * 16;
                        wmma::fragment<wmma::matrix_a, 16, 16, 16, __half,
                                       wmma::row_major> af;
                        wmma::load_matrix_sync(
                            af,
                            &sA[((warp_row + dy) * 130 + px + dx) * AROWH + s * 16],
                            AROWH);
#pragma unroll
                        for (int nf = 0; nf < NF; nf++)
                            wmma::mma_sync(acc[mf][nf], af, bf[nf], acc[mf][nf]);
                    }
                }
            }
        }
    }

    // ---- epilogue ----
    int y = y0 + warp_row;
    if (OUT_FP16_NHWC) {
        __half* outp = (__half*)out_raw;
        __syncthreads();                     // A/B dead; reuse smem as staging
        float* buf = (float*)smh + wid * 320;   // 16 x 20 fp32 per warp
        int r  = lane >> 1;
        int hp = lane & 1;
#pragma unroll
        for (int mf = 0; mf < 4; mf++) {
            int px = warp_pxh * 64 + mf * 16;
#pragma unroll
            for (int nf = 0; nf < NF; nf++) {
                int oc = oc0 + warp_ocg * OCW + nf * 16;
                wmma::store_matrix_sync(buf, acc[mf][nf], 20, wmma::mem_row_major);
                __syncwarp();
                float4 a = *(float4*)&buf[r * 20 + hp * 8];
                float4 b = *(float4*)&buf[r * 20 + hp * 8 + 4];
                __half2 h[4];
                h[0] = __floats2half2_rn(a.x, a.y);
                h[1] = __floats2half2_rn(a.z, a.w);
                h[2] = __floats2half2_rn(b.x, b.y);
                h[3] = __floats2half2_rn(b.z, b.w);
                *(uint4*)&outp[(((size_t)img * H_IMG + y) * W_IMG + px + r) * OC + oc + hp * 8] =
                    *(uint4*)h;
                __syncwarp();
            }
        }
    } else {
        float* outp = (float*)out_raw;       // NCHW fp32 (d_out)
#pragma unroll
        for (int mf = 0; mf < 4; mf++) {
            int px = warp_pxh * 64 + mf * 16;
#pragma unroll
            for (int nf = 0; nf < NF; nf++) {
                int oc = oc0 + warp_ocg * OCW + nf * 16;
                float* dst = &outp[(((size_t)img * OC + oc) * H_IMG + y) * W_IMG + px];
                wmma::store_matrix_sync(dst, acc[mf][nf], HW, wmma::mem_col_major);
            }
        }
    }
}

// ---------------------------------------------------------------------------
// Kernel 4: windowed attention; q/kv fp16 NHWC in, out fp16 NHWC.
// ---------------------------------------------------------------------------
__global__ void attn_kernel(const __half* __restrict__ q,
                            const __half* __restrict__ kv,
                            const float* __restrict__ stat,
                            __half* __restrict__ outp)
{
    int win = blockIdx.x;         // 0..1023
    int hh  = blockIdx.y;         // 0..7
    int bb  = blockIdx.z;         // 0..1
    int wy = win >> 5, wx = win & 31;

    __shared__ float sq[Q_L][DIM_HEAD + 1];
    __shared__ float sk[KV_L][DIM_HEAD + 1];
    __shared__ float sv[KV_L][DIM_HEAD + 1];
    __shared__ float ssim[Q_L][KV_L + 1];

    int tid = threadIdx.x;        // 0..127

    // load q: 16 px x 8 half8-groups (uint4)
    for (int i = tid; i < Q_L * 8; i += 128) {
        int pi = i >> 3, c8 = i & 7;
        int py = pi >> 2, px = pi & 3;
        int pix = (wy * 4 + py) * W_IMG + wx * 4 + px;
        uint4 d = *(const uint4*)&q[((size_t)bb * HW + pix) * INNER + hh * DIM_HEAD + c8 * 8];
        const __half2* h = (const __half2*)&d;
#pragma unroll
        for (int t = 0; t < 4; t++) {
            float2 f = __half22float2(h[t]);
            sq[pi][c8*8 + t*2]     = f.x * 0.125f;
            sq[pi][c8*8 + t*2 + 1] = f.y * 0.125f;
        }
    }
    // load k, v: 48 px x 8 half8-groups each
    for (int i = tid; i < KV_L * 8; i += 128) {
        int j = i >> 3, c8 = i & 7;
        int f = j >> 4, pi = j & 15;
        int py = pi >> 2, px = pi & 3;
        int pix = (wy * 4 + py) * W_IMG + wx * 4 + px;
        size_t base = ((size_t)(bb * 3 + f) * HW + pix) * (2 * INNER) + hh * DIM_HEAD + c8 * 8;
        uint4 dk = *(const uint4*)&kv[base];
        uint4 dv = *(const uint4*)&kv[base + INNER];
        const __half2* hk = (const __half2*)&dk;
        const __half2* hv = (const __half2*)&dv;
#pragma unroll
        for (int t = 0; t < 4; t++) {
            float2 fk = __half22float2(hk[t]);
            float2 fv = __half22float2(hv[t]);
            sk[j][c8*8 + t*2]     = fk.x;
            sk[j][c8*8 + t*2 + 1] = fk.y;
            sv[j][c8*8 + t*2]     = fv.x;
            sv[j][c8*8 + t*2 + 1] = fv.y;
        }
    }
    __syncthreads();

    for (int e = tid; e < Q_L * KV_L; e += 128) {
        int i = e / KV_L, j = e % KV_L;
        float s = 0.f;
#pragma unroll
        for (int d = 0; d < DIM_HEAD; d++) s += sq[i][d] * sk[j][d];
        ssim[i][j] = s + stat[((size_t)hh * Q_L + i) * KV_L + j];
    }
    __syncthreads();

    if (tid < Q_L) {
        float m = -1e30f;
        for (int j = 0; j < KV_L; j++) m = fmaxf(m, ssim[tid][j]);
        float ssum = 0.f;
        for (int j = 0; j < KV_L; j++) {
            float e = expf(ssim[tid][j] - m);
            ssim[tid][j] = e; ssum += e;
        }
        float inv = 1.f / ssum;
        for (int j = 0; j < KV_L; j++) ssim[tid][j] *= inv;
    }
    __syncthreads();

    for (int e = tid; e < Q_L * Q_L; e += 128) {   // 16 px x 16 4-ch groups
        int pi = e >> 4, c = e & 15;
        float r[4];
#pragma unroll
        for (int t = 0; t < 4; t++) {
            int d = c * 4 + t;
            float s = 0.f;
#pragma unroll
            for (int j = 0; j < KV_L; j++) s += ssim[pi][j] * sv[j][d];
            r[t] = s;
        }
        int py = pi >> 2, px = pi & 3;
        int pix = (wy * 4 + py) * W_IMG + wx * 4 + px;
        __half2* op = (__half2*)&outp[((size_t)bb * HW + pix) * INNER + hh * DIM_HEAD + c * 4];
        op[0] = __floats2half2_rn(r[0], r[1]);
        op[1] = __floats2half2_rn(r[2], r[3]);
    }
}

// ---------------------------------------------------------------------------
// Host launch
// ---------------------------------------------------------------------------
extern "C" void kernel_launch(void* const* d_in, const int* in_sizes, int n_in,
                              void* d_out, int out_size)
{
    (void)in_sizes; (void)n_in; (void)out_size;

    const float* q_inp   = (const float*)d_in[0];
    const float* k_inp   = (const float*)d_in[1];
    const float* flow_f  = (const float*)d_in[2];
    const float* flow_b  = (const float*)d_in[3];
    const float* gq      = (const float*)d_in[4];
    const float* bq      = (const float*)d_in[5];
    const float* gkv     = (const float*)d_in[6];
    const float* bkv     = (const float*)d_in[7];
    const float* Wq      = (const float*)d_in[8];
    const float* Wkv     = (const float*)d_in[9];
    const float* Wout    = (const float*)d_in[10];
    const float* statica = (const float*)d_in[11];

    __half *qn, *kvn, *qb, *kvb, *attb, *wtq, *wtkv, *wtout;
    cudaGetSymbolAddress((void**)&qn,    g_qn);
    cudaGetSymbolAddress((void**)&kvn,   g_kvn);
    cudaGetSymbolAddress((void**)&qb,    g_q);
    cudaGetSymbolAddress((void**)&kvb,   g_kv);
    cudaGetSymbolAddress((void**)&attb,  g_att);
    cudaGetSymbolAddress((void**)&wtq,   g_wt_q);
    cudaGetSymbolAddress((void**)&wtkv,  g_wt_kv);
    cudaGetSymbolAddress((void**)&wtout, g_wt_out);

    const int SMEM128 = (A_ELEMSH + 3 * 128 * AROWH) * 2;   // 130,176 B
    const int SMEM64  = (A_ELEMSH + 3 * 64  * AROWH) * 2;   // 102,528 B
    cudaFuncSetAttribute((const void*)conv3x3_h_kernel<128, true>,
                         cudaFuncAttributeMaxDynamicSharedMemorySize, SMEM128);
    cudaFuncSetAttribute((const void*)conv3x3_h_kernel<64, false>,
                         cudaFuncAttributeMaxDynamicSharedMemorySize, SMEM64);

    // 0) weight transforms (fp16)
    wtrans_kernel<<<(INNER * C_DIM + 255) / 256, 256>>>(Wq, wtq, INNER, C_DIM);
    wtrans_kernel<<<(2 * INNER * C_DIM + 255) / 256, 256>>>(Wkv, wtkv, 2 * INNER, C_DIM);
    wtrans_kernel<<<(C_DIM * INNER + 255) / 256, 256>>>(Wout, wtout, C_DIM, INNER);

    // 1) layernorm q  (NHWC fp16)
    ln_q_kernel<<<dim3(HW / 256, 1, B), 256>>>(q_inp, gq, bq, qn);

    // 2) warp + stack + layernorm kv  (NHWC fp16)
    warp_ln_kv_kernel<<<dim3(HW / 256, 3, B), 256>>>(k_inp, flow_f, flow_b, gkv, bkv, kvn);

    // 3) conv q: 64 -> 512, NHWC fp16 out
    conv3x3_h_kernel<128, true><<<dim3(H_IMG / 2, INNER / 128, B), 256, SMEM128>>>(
        qn, wtq, qb, C_DIM, INNER);

    // 4) conv kv: 64 -> 1024, NHWC fp16 out
    conv3x3_h_kernel<128, true><<<dim3(H_IMG / 2, (2 * INNER) / 128, B * 3), 256, SMEM128>>>(
        kvn, wtkv, kvb, C_DIM, 2 * INNER);

    // 5) attention (fp16 in, fp16 NHWC out)
    attn_kernel<<<dim3(1024, HEADS, B), 128>>>(qb, kvb, statica, attb);

    // 6) conv out: 512 -> 64, fp32 NCHW out -> d_out
    conv3x3_h_kernel<64, false><<<dim3(H_IMG / 2, 1, B), 256, SMEM64>>>(
        attb, wtout, (float*)d_out, INNER, C_DIM);
}

// round 8
// speedup vs baseline: 5.9247x; 1.0648x over previous
#include <cuda_runtime.h>
#include <cuda_fp16.h>
#include <mma.h>
#include <math.h>
#include <stdint.h>

using namespace nvcuda;

// ---------------------------------------------------------------------------
// Problem constants
// ---------------------------------------------------------------------------
#define B       2
#define C_DIM   64
#define H_IMG   128
#define W_IMG   128
#define HW      (H_IMG * W_IMG)          // 16384
#define HEADS   8
#define DIM_HEAD 64
#define INNER   (HEADS * DIM_HEAD)       // 512
#define Q_L     16
#define KV_L    48
#define LN_EPS  1e-5f

// ---------------------------------------------------------------------------
// Scratch buffers (__device__ globals; allocation is forbidden)
// ---------------------------------------------------------------------------
__device__ __half g_qn  [B * HW * C_DIM];            // LN(q), NHWC fp16
__device__ __half g_kvn [B * 3 * HW * C_DIM];        // warped+LN kv, NHWC fp16
__device__ __half g_q   [B * HW * INNER];            // conv q out, NHWC fp16
__device__ __half g_kv  [B * 3 * HW * 2 * INNER];    // conv kv out, NHWC fp16
__device__ __half g_att [B * HW * INNER];            // attention out, NHWC fp16
__device__ __half g_wt_q  [9 * INNER * C_DIM];       // Wq  as [tap][oc][ic] fp16
__device__ __half g_wt_kv [9 * 2 * INNER * C_DIM];   // Wkv as [tap][oc][ic] fp16
__device__ __half g_wt_out[9 * C_DIM * INNER];       // Wout as [tap][oc][ic] fp16

// ---------------------------------------------------------------------------
// Kernel 0: weight transform  W[oc][ic][3][3] -> Wt[tap][oc][ic] (fp16)
// ---------------------------------------------------------------------------
__global__ void wtrans_kernel(const float* __restrict__ W,
                              __half* __restrict__ Wt, int OC, int IC)
{
    int idx = blockIdx.x * blockDim.x + threadIdx.x;
    if (idx >= OC * IC) return;
    int oc = idx / IC, ic = idx % IC;
    const float* src = W + ((size_t)oc * IC + ic) * 9;
#pragma unroll
    for (int t = 0; t < 9; t++)
        Wt[((size_t)t * OC + oc) * IC + ic] = __float2half_rn(src[t]);
}

// ---------------------------------------------------------------------------
// Kernel 1: LayerNorm q -> NHWC fp16
// ---------------------------------------------------------------------------
__global__ void ln_q_kernel(const float* __restrict__ q_inp,
                            const float* __restrict__ g,
                            const float* __restrict__ beta,
                            __half* __restrict__ out)
{
    int pix = blockIdx.x * blockDim.x + threadIdx.x;
    if (pix >= HW) return;
    int bb = blockIdx.z;

    const float* base = q_inp + ((size_t)bb * C_DIM) * HW + pix;
    float vals[C_DIM];
    float sum = 0.f;
#pragma unroll
    for (int c = 0; c < C_DIM; c++) { float v = base[(size_t)c * HW]; vals[c] = v; sum += v; }
    float mu = sum * (1.f / C_DIM);
    float var = 0.f;
#pragma unroll
    for (int c = 0; c < C_DIM; c++) { float d = vals[c] - mu; var += d * d; }
    var *= (1.f / C_DIM);
    float inv = rsqrtf(var + LN_EPS);

    __half2* ob = (__half2*)(out + ((size_t)bb * HW + pix) * C_DIM);
#pragma unroll
    for (int c = 0; c < C_DIM; c += 2)
        ob[c >> 1] = __floats2half2_rn((vals[c]   - mu) * inv * g[c]   + beta[c],
                                       (vals[c+1] - mu) * inv * g[c+1] + beta[c+1]);
}

// ---------------------------------------------------------------------------
// Kernel 2: flow warp + stack + LayerNorm kv -> NHWC fp16
// ---------------------------------------------------------------------------
__global__ void warp_ln_kv_kernel(const float* __restrict__ k_inp,
                                  const float* __restrict__ flow_f,
                                  const float* __restrict__ flow_b,
                                  const float* __restrict__ g,
                                  const float* __restrict__ beta,
                                  __half* __restrict__ out)
{
    int pix = blockIdx.x * blockDim.x + threadIdx.x;
    if (pix >= HW) return;
    int f  = blockIdx.y;   // 0..2
    int bb = blockIdx.z;   // 0..1
    int y = pix >> 7, x = pix & 127;

    int src = pix;
    bool valid = true;
    if (f != 1) {
        const float* fl = (f == 0) ? flow_f : flow_b;
        float fx = fl[((size_t)bb * 2 + 0) * HW + pix];
        float fy = fl[((size_t)bb * 2 + 1) * HW + pix];
        int ix = (int)rintf((float)x + fx);
        int iy = (int)rintf((float)y + fy);
        valid = (ix >= 0) && (ix < W_IMG) && (iy >= 0) && (iy < H_IMG);
        int cx = min(max(ix, 0), W_IMG - 1);
        int cy = min(max(iy, 0), H_IMG - 1);
        src = cy * W_IMG + cx;
    }

    const float* base = k_inp + (((size_t)bb * 3 + f) * C_DIM) * HW + src;
    float vals[C_DIM];
    float sum = 0.f;
#pragma unroll
    for (int c = 0; c < C_DIM; c++) {
        float v = valid ? base[(size_t)c * HW] : 0.f;
        vals[c] = v; sum += v;
    }
    float mu = sum * (1.f / C_DIM);
    float var = 0.f;
#pragma unroll
    for (int c = 0; c < C_DIM; c++) { float d = vals[c] - mu; var += d * d; }
    var *= (1.f / C_DIM);
    float inv = rsqrtf(var + LN_EPS);

    __half2* ob = (__half2*)(out + (((size_t)(bb * 3 + f)) * HW + pix) * C_DIM);
#pragma unroll
    for (int c = 0; c < C_DIM; c += 2)
        ob[c >> 1] = __floats2half2_rn((vals[c]   - mu) * inv * g[c]   + beta[c],
                                       (vals[c+1] - mu) * inv * g[c+1] + beta[c+1]);
}

// ---------------------------------------------------------------------------
// Kernel 3: 3x3 conv as implicit GEMM on wmma fp16 (m16n16k16, fp32 accum).
// One CTA = ROWS image rows (M = ROWS*128 px) x N_TILE=64 output channels.
// A: SMEM [(ROWS+2) rows][130 px][72 halfs]; B: SMEM [9 taps][64 oc][72 halfs]
// -> ALL taps staged once per IC chunk; exactly 2 barriers per chunk.
// 8 warps = ROWS rows x 2 px-halves x (8/(2*ROWS)) oc-groups.
// ---------------------------------------------------------------------------
#define AROWH 72                            // halfs per px (64 + 8 pad)

template <int ROWS, bool OUT_FP16_NHWC>
__global__ __launch_bounds__(256, 1)
void conv3x3_h_kernel(const __half* __restrict__ in,   // NHWC fp16
                      const __half* __restrict__ Wt,   // [9][OC][IC] fp16
                      void* __restrict__ out_raw,
                      int IC, int OC)
{
    constexpr int N_TILE = 64;
    constexpr int NOCG = 8 / (2 * ROWS);     // oc groups (1 for ROWS=4, 2 for ROWS=2)
    constexpr int OCW  = N_TILE / NOCG;      // oc per warp (64 or 32)
    constexpr int NF   = OCW / 16;           // B fragments per warp (4 or 2)
    constexpr int A_ELEMS = (ROWS + 2) * 130 * AROWH;

    extern __shared__ __half smh[];
    __half* sA = smh;                        // [(ROWS+2)][130][AROWH]
    __half* sB = smh + A_ELEMS;              // [9][N_TILE][AROWH]

    int tid  = threadIdx.x;
    int wid  = tid >> 5;
    int lane = tid & 31;

    int y0  = blockIdx.x * ROWS;
    int oc0 = blockIdx.y * N_TILE;
    int img = blockIdx.z;

    int warp_row = wid % ROWS;
    int warp_pxh = (wid / ROWS) & 1;         // 0..1 (64 px each)
    int warp_ocg = wid / (2 * ROWS);         // 0..NOCG-1

    wmma::fragment<wmma::accumulator, 16, 16, 16, float> acc[4][NF];
#pragma unroll
    for (int mf = 0; mf < 4; mf++)
#pragma unroll
        for (int nf = 0; nf < NF; nf++) wmma::fill_fragment(acc[mf][nf], 0.0f);

    const int chunks = IC / 64;

    for (int c = 0; c < chunks; c++) {
        int ic0 = c * 64;

        __syncthreads();
        // ---- stage A: (ROWS+2) rows x 130 px x 64 ic (16B copies) ----
        for (int i = tid; i < (ROWS + 2) * 130 * 8; i += 256) {
            int r   = i / (130 * 8);
            int rem = i % (130 * 8);
            int p   = rem >> 3;
            int v   = rem & 7;
            int gy = y0 + r - 1, gx = p - 1;
            uint4 d = make_uint4(0u, 0u, 0u, 0u);
            if (gy >= 0 && gy < H_IMG && gx >= 0 && gx < W_IMG)
                d = *(const uint4*)&in[(((size_t)img * H_IMG + gy) * W_IMG + gx) * IC + ic0 + v * 8];
            *(uint4*)&sA[(r * 130 + p) * AROWH + v * 8] = d;
        }
        // ---- stage B: ALL 9 taps x 64 oc x 64 ic ----
        for (int i = tid; i < 9 * N_TILE * 8; i += 256) {
            int tap = i / (N_TILE * 8);
            int rem = i % (N_TILE * 8);
            int o   = rem >> 3;
            int v   = rem & 7;
            *(uint4*)&sB[(tap * N_TILE + o) * AROWH + v * 8] =
                *(const uint4*)&Wt[(((size_t)tap * OC) + oc0 + o) * IC + ic0 + v * 8];
        }
        __syncthreads();

        // ---- compute: 9 taps x 4 k-steps, no barriers ----
#pragma unroll
        for (int dy = 0; dy < 3; dy++) {
#pragma unroll
            for (int dx = 0; dx < 3; dx++) {
                const int tap = dy * 3 + dx;
#pragma unroll
                for (int s = 0; s < 4; s++) {
                    wmma::fragment<wmma::matrix_b, 16, 16, 16, __half,
                                   wmma::col_major> bf[NF];
#pragma unroll
                    for (int nf = 0; nf < NF; nf++)
                        wmma::load_matrix_sync(
                            bf[nf],
                            &sB[(tap * N_TILE + warp_ocg * OCW + nf * 16) * AROWH + s * 16],
                            AROWH);
#pragma unroll
                    for (int mf = 0; mf < 4; mf++) {
                        int px = warp_pxh * 64 + mf * 16;
                        wmma::fragment<wmma::matrix_a, 16, 16, 16, __half,
                                       wmma::row_major> af;
                        wmma::load_matrix_sync(
                            af,
                            &sA[((warp_row + dy) * 130 + px + dx) * AROWH + s * 16],
                            AROWH);
#pragma unroll
                        for (int nf = 0; nf < NF; nf++)
                            wmma::mma_sync(acc[mf][nf], af, bf[nf], acc[mf][nf]);
                    }
                }
            }
        }
    }

    // ---- epilogue ----
    int y = y0 + warp_row;
    if (OUT_FP16_NHWC) {
        __half* outp = (__half*)out_raw;
        __syncthreads();                     // A/B dead; reuse smem as staging
        float* buf = (float*)smh + wid * 320;   // 16 x 20 fp32 per warp
        int r  = lane >> 1;
        int hp = lane & 1;
#pragma unroll
        for (int mf = 0; mf < 4; mf++) {
            int px = warp_pxh * 64 + mf * 16;
#pragma unroll
            for (int nf = 0; nf < NF; nf++) {
                int oc = oc0 + warp_ocg * OCW + nf * 16;
                wmma::store_matrix_sync(buf, acc[mf][nf], 20, wmma::mem_row_major);
                __syncwarp();
                float4 a = *(float4*)&buf[r * 20 + hp * 8];
                float4 b = *(float4*)&buf[r * 20 + hp * 8 + 4];
                __half2 h[4];
                h[0] = __floats2half2_rn(a.x, a.y);
                h[1] = __floats2half2_rn(a.z, a.w);
                h[2] = __floats2half2_rn(b.x, b.y);
                h[3] = __floats2half2_rn(b.z, b.w);
                *(uint4*)&outp[(((size_t)img * H_IMG + y) * W_IMG + px + r) * OC + oc + hp * 8] =
                    *(uint4*)h;
                __syncwarp();
            }
        }
    } else {
        float* outp = (float*)out_raw;       // NCHW fp32 (d_out)
#pragma unroll
        for (int mf = 0; mf < 4; mf++) {
            int px = warp_pxh * 64 + mf * 16;
#pragma unroll
            for (int nf = 0; nf < NF; nf++) {
                int oc = oc0 + warp_ocg * OCW + nf * 16;
                float* dst = &outp[(((size_t)img * OC + oc) * H_IMG + y) * W_IMG + px];
                wmma::store_matrix_sync(dst, acc[mf][nf], HW, wmma::mem_col_major);
            }
        }
    }
}

// ---------------------------------------------------------------------------
// Kernel 4: windowed attention; q/kv fp16 NHWC in, out fp16 NHWC.
// ---------------------------------------------------------------------------
__global__ void attn_kernel(const __half* __restrict__ q,
                            const __half* __restrict__ kv,
                            const float* __restrict__ stat,
                            __half* __restrict__ outp)
{
    int win = blockIdx.x;         // 0..1023
    int hh  = blockIdx.y;         // 0..7
    int bb  = blockIdx.z;         // 0..1
    int wy = win >> 5, wx = win & 31;

    __shared__ float sq[Q_L][DIM_HEAD + 1];
    __shared__ float sk[KV_L][DIM_HEAD + 1];
    __shared__ float sv[KV_L][DIM_HEAD + 1];
    __shared__ float ssim[Q_L][KV_L + 1];

    int tid = threadIdx.x;        // 0..127

    for (int i = tid; i < Q_L * 8; i += 128) {
        int pi = i >> 3, c8 = i & 7;
        int py = pi >> 2, px = pi & 3;
        int pix = (wy * 4 + py) * W_IMG + wx * 4 + px;
        uint4 d = *(const uint4*)&q[((size_t)bb * HW + pix) * INNER + hh * DIM_HEAD + c8 * 8];
        const __half2* h = (const __half2*)&d;
#pragma unroll
        for (int t = 0; t < 4; t++) {
            float2 f = __half22float2(h[t]);
            sq[pi][c8*8 + t*2]     = f.x * 0.125f;
            sq[pi][c8*8 + t*2 + 1] = f.y * 0.125f;
        }
    }
    for (int i = tid; i < KV_L * 8; i += 128) {
        int j = i >> 3, c8 = i & 7;
        int f = j >> 4, pi = j & 15;
        int py = pi >> 2, px = pi & 3;
        int pix = (wy * 4 + py) * W_IMG + wx * 4 + px;
        size_t base = ((size_t)(bb * 3 + f) * HW + pix) * (2 * INNER) + hh * DIM_HEAD + c8 * 8;
        uint4 dk = *(const uint4*)&kv[base];
        uint4 dv = *(const uint4*)&kv[base + INNER];
        const __half2* hk = (const __half2*)&dk;
        const __half2* hv = (const __half2*)&dv;
#pragma unroll
        for (int t = 0; t < 4; t++) {
            float2 fk = __half22float2(hk[t]);
            float2 fv = __half22float2(hv[t]);
            sk[j][c8*8 + t*2]     = fk.x;
            sk[j][c8*8 + t*2 + 1] = fk.y;
            sv[j][c8*8 + t*2]     = fv.x;
            sv[j][c8*8 + t*2 + 1] = fv.y;
        }
    }
    __syncthreads();

    for (int e = tid; e < Q_L * KV_L; e += 128) {
        int i = e / KV_L, j = e % KV_L;
        float s = 0.f;
#pragma unroll
        for (int d = 0; d < DIM_HEAD; d++) s += sq[i][d] * sk[j][d];
        ssim[i][j] = s + stat[((size_t)hh * Q_L + i) * KV_L + j];
    }
    __syncthreads();

    if (tid < Q_L) {
        float m = -1e30f;
        for (int j = 0; j < KV_L; j++) m = fmaxf(m, ssim[tid][j]);
        float ssum = 0.f;
        for (int j = 0; j < KV_L; j++) {
            float e = expf(ssim[tid][j] - m);
            ssim[tid][j] = e; ssum += e;
        }
        float inv = 1.f / ssum;
        for (int j = 0; j < KV_L; j++) ssim[tid][j] *= inv;
    }
    __syncthreads();

    for (int e = tid; e < Q_L * Q_L; e += 128) {   // 16 px x 16 4-ch groups
        int pi = e >> 4, c = e & 15;
        float r[4];
#pragma unroll
        for (int t = 0; t < 4; t++) {
            int d = c * 4 + t;
            float s = 0.f;
#pragma unroll
            for (int j = 0; j < KV_L; j++) s += ssim[pi][j] * sv[j][d];
            r[t] = s;
        }
        int py = pi >> 2, px = pi & 3;
        int pix = (wy * 4 + py) * W_IMG + wx * 4 + px;
        __half2* op = (__half2*)&outp[((size_t)bb * HW + pix) * INNER + hh * DIM_HEAD + c * 4];
        op[0] = __floats2half2_rn(r[0], r[1]);
        op[1] = __floats2half2_rn(r[2], r[3]);
    }
}

// ---------------------------------------------------------------------------
// Host launch
// ---------------------------------------------------------------------------
extern "C" void kernel_launch(void* const* d_in, const int* in_sizes, int n_in,
                              void* d_out, int out_size)
{
    (void)in_sizes; (void)n_in; (void)out_size;

    const float* q_inp   = (const float*)d_in[0];
    const float* k_inp   = (const float*)d_in[1];
    const float* flow_f  = (const float*)d_in[2];
    const float* flow_b  = (const float*)d_in[3];
    const float* gq      = (const float*)d_in[4];
    const float* bq      = (const float*)d_in[5];
    const float* gkv     = (const float*)d_in[6];
    const float* bkv     = (const float*)d_in[7];
    const float* Wq      = (const float*)d_in[8];
    const float* Wkv     = (const float*)d_in[9];
    const float* Wout    = (const float*)d_in[10];
    const float* statica = (const float*)d_in[11];

    __half *qn, *kvn, *qb, *kvb, *attb, *wtq, *wtkv, *wtout;
    cudaGetSymbolAddress((void**)&qn,    g_qn);
    cudaGetSymbolAddress((void**)&kvn,   g_kvn);
    cudaGetSymbolAddress((void**)&qb,    g_q);
    cudaGetSymbolAddress((void**)&kvb,   g_kv);
    cudaGetSymbolAddress((void**)&attb,  g_att);
    cudaGetSymbolAddress((void**)&wtq,   g_wt_q);
    cudaGetSymbolAddress((void**)&wtkv,  g_wt_kv);
    cudaGetSymbolAddress((void**)&wtout, g_wt_out);

    const int SMEM4 = ((4 + 2) * 130 * AROWH + 9 * 64 * AROWH) * 2;   // 195,264 B
    const int SMEM2 = ((2 + 2) * 130 * AROWH + 9 * 64 * AROWH) * 2;   // 157,824 B
    cudaFuncSetAttribute((const void*)conv3x3_h_kernel<4, true>,
                         cudaFuncAttributeMaxDynamicSharedMemorySize, SMEM4);
    cudaFuncSetAttribute((const void*)conv3x3_h_kernel<2, false>,
                         cudaFuncAttributeMaxDynamicSharedMemorySize, SMEM2);

    // 0) weight transforms (fp16)
    wtrans_kernel<<<(INNER * C_DIM + 255) / 256, 256>>>(Wq, wtq, INNER, C_DIM);
    wtrans_kernel<<<(2 * INNER * C_DIM + 255) / 256, 256>>>(Wkv, wtkv, 2 * INNER, C_DIM);
    wtrans_kernel<<<(C_DIM * INNER + 255) / 256, 256>>>(Wout, wtout, C_DIM, INNER);

    // 1) layernorm q  (NHWC fp16)
    ln_q_kernel<<<dim3(HW / 256, 1, B), 256>>>(q_inp, gq, bq, qn);

    // 2) warp + stack + layernorm kv  (NHWC fp16)
    warp_ln_kv_kernel<<<dim3(HW / 256, 3, B), 256>>>(k_inp, flow_f, flow_b, gkv, bkv, kvn);

    // 3) conv q: 64 -> 512, NHWC fp16 out  (4-row strips, 64 oc/CTA)
    conv3x3_h_kernel<4, true><<<dim3(H_IMG / 4, INNER / 64, B), 256, SMEM4>>>(
        qn, wtq, qb, C_DIM, INNER);

    // 4) conv kv: 64 -> 1024, NHWC fp16 out
    conv3x3_h_kernel<4, true><<<dim3(H_IMG / 4, (2 * INNER) / 64, B * 3), 256, SMEM4>>>(
        kvn, wtkv, kvb, C_DIM, 2 * INNER);

    // 5) attention (fp16 in, fp16 NHWC out)
    attn_kernel<<<dim3(1024, HEADS, B), 128>>>(qb, kvb, statica, attb);

    // 6) conv out: 512 -> 64, fp32 NCHW out -> d_out  (2-row strips)
    conv3x3_h_kernel<2, false><<<dim3(H_IMG / 2, 1, B), 256, SMEM2>>>(
        attb, wtout, (float*)d_out, INNER, C_DIM);
}

// round 9
// speedup vs baseline: 7.8167x; 1.3193x over previous
#include <cuda_runtime.h>
#include <cuda_fp16.h>
#include <mma.h>
#include <math.h>
#include <stdint.h>

using namespace nvcuda;

// ---------------------------------------------------------------------------
// Problem constants
// ---------------------------------------------------------------------------
#define B       2
#define C_DIM   64
#define H_IMG   128
#define W_IMG   128
#define HW      (H_IMG * W_IMG)          // 16384
#define HEADS   8
#define DIM_HEAD 64
#define INNER   (HEADS * DIM_HEAD)       // 512
#define Q_L     16
#define KV_L    48
#define LN_EPS  1e-5f

// ---------------------------------------------------------------------------
// Scratch buffers (__device__ globals; allocation is forbidden)
// ---------------------------------------------------------------------------
__device__ __half g_qn  [B * HW * C_DIM];            // LN(q), NHWC fp16
__device__ __half g_kvn [B * 3 * HW * C_DIM];        // warped+LN kv, NHWC fp16
__device__ __half g_q   [B * HW * INNER];            // conv q out, NHWC fp16 (pre-scaled)
__device__ __half g_kv  [B * 3 * HW * 2 * INNER];    // conv kv out, NHWC fp16
__device__ __half g_att [B * HW * INNER];            // attention out, NHWC fp16
__device__ __half g_wt_q  [9 * INNER * C_DIM];       // Wq*0.125 as [tap][oc][ic] fp16
__device__ __half g_wt_kv [9 * 2 * INNER * C_DIM];   // Wkv as [tap][oc][ic] fp16
__device__ __half g_wt_out[9 * C_DIM * INNER];       // Wout as [tap][oc][ic] fp16

// ---------------------------------------------------------------------------
// Kernel 0: weight transform  W[oc][ic][3][3] -> Wt[tap][oc][ic] (fp16, scaled)
// ---------------------------------------------------------------------------
__global__ void wtrans_kernel(const float* __restrict__ W,
                              __half* __restrict__ Wt, int OC, int IC,
                              float scale)
{
    int idx = blockIdx.x * blockDim.x + threadIdx.x;
    if (idx >= OC * IC) return;
    int oc = idx / IC, ic = idx % IC;
    const float* src = W + ((size_t)oc * IC + ic) * 9;
#pragma unroll
    for (int t = 0; t < 9; t++)
        Wt[((size_t)t * OC + oc) * IC + ic] = __float2half_rn(src[t] * scale);
}

// ---------------------------------------------------------------------------
// Kernel 1: LayerNorm q -> NHWC fp16
// ---------------------------------------------------------------------------
__global__ void ln_q_kernel(const float* __restrict__ q_inp,
                            const float* __restrict__ g,
                            const float* __restrict__ beta,
                            __half* __restrict__ out)
{
    int pix = blockIdx.x * blockDim.x + threadIdx.x;
    if (pix >= HW) return;
    int bb = blockIdx.z;

    const float* base = q_inp + ((size_t)bb * C_DIM) * HW + pix;
    float vals[C_DIM];
    float sum = 0.f;
#pragma unroll
    for (int c = 0; c < C_DIM; c++) { float v = base[(size_t)c * HW]; vals[c] = v; sum += v; }
    float mu = sum * (1.f / C_DIM);
    float var = 0.f;
#pragma unroll
    for (int c = 0; c < C_DIM; c++) { float d = vals[c] - mu; var += d * d; }
    var *= (1.f / C_DIM);
    float inv = rsqrtf(var + LN_EPS);

    __half2* ob = (__half2*)(out + ((size_t)bb * HW + pix) * C_DIM);
#pragma unroll
    for (int c = 0; c < C_DIM; c += 2)
        ob[c >> 1] = __floats2half2_rn((vals[c]   - mu) * inv * g[c]   + beta[c],
                                       (vals[c+1] - mu) * inv * g[c+1] + beta[c+1]);
}

// ---------------------------------------------------------------------------
// Kernel 2: flow warp + stack + LayerNorm kv -> NHWC fp16
// ---------------------------------------------------------------------------
__global__ void warp_ln_kv_kernel(const float* __restrict__ k_inp,
                                  const float* __restrict__ flow_f,
                                  const float* __restrict__ flow_b,
                                  const float* __restrict__ g,
                                  const float* __restrict__ beta,
                                  __half* __restrict__ out)
{
    int pix = blockIdx.x * blockDim.x + threadIdx.x;
    if (pix >= HW) return;
    int f  = blockIdx.y;   // 0..2
    int bb = blockIdx.z;   // 0..1
    int y = pix >> 7, x = pix & 127;

    int src = pix;
    bool valid = true;
    if (f != 1) {
        const float* fl = (f == 0) ? flow_f : flow_b;
        float fx = fl[((size_t)bb * 2 + 0) * HW + pix];
        float fy = fl[((size_t)bb * 2 + 1) * HW + pix];
        int ix = (int)rintf((float)x + fx);
        int iy = (int)rintf((float)y + fy);
        valid = (ix >= 0) && (ix < W_IMG) && (iy >= 0) && (iy < H_IMG);
        int cx = min(max(ix, 0), W_IMG - 1);
        int cy = min(max(iy, 0), H_IMG - 1);
        src = cy * W_IMG + cx;
    }

    const float* base = k_inp + (((size_t)bb * 3 + f) * C_DIM) * HW + src;
    float vals[C_DIM];
    float sum = 0.f;
#pragma unroll
    for (int c = 0; c < C_DIM; c++) {
        float v = valid ? base[(size_t)c * HW] : 0.f;
        vals[c] = v; sum += v;
    }
    float mu = sum * (1.f / C_DIM);
    float var = 0.f;
#pragma unroll
    for (int c = 0; c < C_DIM; c++) { float d = vals[c] - mu; var += d * d; }
    var *= (1.f / C_DIM);
    float inv = rsqrtf(var + LN_EPS);

    __half2* ob = (__half2*)(out + (((size_t)(bb * 3 + f)) * HW + pix) * C_DIM);
#pragma unroll
    for (int c = 0; c < C_DIM; c += 2)
        ob[c >> 1] = __floats2half2_rn((vals[c]   - mu) * inv * g[c]   + beta[c],
                                       (vals[c+1] - mu) * inv * g[c+1] + beta[c+1]);
}

// ---------------------------------------------------------------------------
// Kernel 3: 3x3 conv as implicit GEMM on wmma fp16 (m16n16k16, fp32 accum).
// One CTA = ROWS image rows x 64 output channels; all 9 taps staged once.
// ---------------------------------------------------------------------------
#define AROWH 72                            // halfs per px (64 + 8 pad)

template <int ROWS, bool OUT_FP16_NHWC>
__global__ __launch_bounds__(256, 1)
void conv3x3_h_kernel(const __half* __restrict__ in,   // NHWC fp16
                      const __half* __restrict__ Wt,   // [9][OC][IC] fp16
                      void* __restrict__ out_raw,
                      int IC, int OC)
{
    constexpr int N_TILE = 64;
    constexpr int NOCG = 8 / (2 * ROWS);     // oc groups
    constexpr int OCW  = N_TILE / NOCG;      // oc per warp
    constexpr int NF   = OCW / 16;           // B fragments per warp
    constexpr int A_ELEMS = (ROWS + 2) * 130 * AROWH;

    extern __shared__ __half smh[];
    __half* sA = smh;
    __half* sB = smh + A_ELEMS;

    int tid  = threadIdx.x;
    int wid  = tid >> 5;
    int lane = tid & 31;

    int y0  = blockIdx.x * ROWS;
    int oc0 = blockIdx.y * N_TILE;
    int img = blockIdx.z;

    int warp_row = wid % ROWS;
    int warp_pxh = (wid / ROWS) & 1;
    int warp_ocg = wid / (2 * ROWS);

    wmma::fragment<wmma::accumulator, 16, 16, 16, float> acc[4][NF];
#pragma unroll
    for (int mf = 0; mf < 4; mf++)
#pragma unroll
        for (int nf = 0; nf < NF; nf++) wmma::fill_fragment(acc[mf][nf], 0.0f);

    const int chunks = IC / 64;

    for (int c = 0; c < chunks; c++) {
        int ic0 = c * 64;

        __syncthreads();
        for (int i = tid; i < (ROWS + 2) * 130 * 8; i += 256) {
            int r   = i / (130 * 8);
            int rem = i % (130 * 8);
            int p   = rem >> 3;
            int v   = rem & 7;
            int gy = y0 + r - 1, gx = p - 1;
            uint4 d = make_uint4(0u, 0u, 0u, 0u);
            if (gy >= 0 && gy < H_IMG && gx >= 0 && gx < W_IMG)
                d = *(const uint4*)&in[(((size_t)img * H_IMG + gy) * W_IMG + gx) * IC + ic0 + v * 8];
            *(uint4*)&sA[(r * 130 + p) * AROWH + v * 8] = d;
        }
        for (int i = tid; i < 9 * N_TILE * 8; i += 256) {
            int tap = i / (N_TILE * 8);
            int rem = i % (N_TILE * 8);
            int o   = rem >> 3;
            int v   = rem & 7;
            *(uint4*)&sB[(tap * N_TILE + o) * AROWH + v * 8] =
                *(const uint4*)&Wt[(((size_t)tap * OC) + oc0 + o) * IC + ic0 + v * 8];
        }
        __syncthreads();

#pragma unroll
        for (int dy = 0; dy < 3; dy++) {
#pragma unroll
            for (int dx = 0; dx < 3; dx++) {
                const int tap = dy * 3 + dx;
#pragma unroll
                for (int s = 0; s < 4; s++) {
                    wmma::fragment<wmma::matrix_b, 16, 16, 16, __half,
                                   wmma::col_major> bf[NF];
#pragma unroll
                    for (int nf = 0; nf < NF; nf++)
                        wmma::load_matrix_sync(
                            bf[nf],
                            &sB[(tap * N_TILE + warp_ocg * OCW + nf * 16) * AROWH + s * 16],
                            AROWH);
#pragma unroll
                    for (int mf = 0; mf < 4; mf++) {
                        int px = warp_pxh * 64 + mf * 16;
                        wmma::fragment<wmma::matrix_a, 16, 16, 16, __half,
                                       wmma::row_major> af;
                        wmma::load_matrix_sync(
                            af,
                            &sA[((warp_row + dy) * 130 + px + dx) * AROWH + s * 16],
                            AROWH);
#pragma unroll
                        for (int nf = 0; nf < NF; nf++)
                            wmma::mma_sync(acc[mf][nf], af, bf[nf], acc[mf][nf]);
                    }
                }
            }
        }
    }

    // ---- epilogue ----
    int y = y0 + warp_row;
    if (OUT_FP16_NHWC) {
        __half* outp = (__half*)out_raw;
        __syncthreads();
        float* buf = (float*)smh + wid * 320;
        int r  = lane >> 1;
        int hp = lane & 1;
#pragma unroll
        for (int mf = 0; mf < 4; mf++) {
            int px = warp_pxh * 64 + mf * 16;
#pragma unroll
            for (int nf = 0; nf < NF; nf++) {
                int oc = oc0 + warp_ocg * OCW + nf * 16;
                wmma::store_matrix_sync(buf, acc[mf][nf], 20, wmma::mem_row_major);
                __syncwarp();
                float4 a = *(float4*)&buf[r * 20 + hp * 8];
                float4 b = *(float4*)&buf[r * 20 + hp * 8 + 4];
                __half2 h[4];
                h[0] = __floats2half2_rn(a.x, a.y);
                h[1] = __floats2half2_rn(a.z, a.w);
                h[2] = __floats2half2_rn(b.x, b.y);
                h[3] = __floats2half2_rn(b.z, b.w);
                *(uint4*)&outp[(((size_t)img * H_IMG + y) * W_IMG + px + r) * OC + oc + hp * 8] =
                    *(uint4*)h;
                __syncwarp();
            }
        }
    } else {
        float* outp = (float*)out_raw;
#pragma unroll
        for (int mf = 0; mf < 4; mf++) {
            int px = warp_pxh * 64 + mf * 16;
#pragma unroll
            for (int nf = 0; nf < NF; nf++) {
                int oc = oc0 + warp_ocg * OCW + nf * 16;
                float* dst = &outp[(((size_t)img * OC + oc) * H_IMG + y) * W_IMG + px];
                wmma::store_matrix_sync(dst, acc[mf][nf], HW, wmma::mem_col_major);
            }
        }
    }
}

// ---------------------------------------------------------------------------
// Kernel 4: windowed attention on tensor cores.
// One block = one window (all heads), 256 threads = 8 warps, warp per head.
// sim = q(16x64) k^T : 3n x 4k wmma;  out = p(16x48) v : 4n x 3k wmma.
// q is pre-scaled by 0.125 (folded into Wq).
// ---------------------------------------------------------------------------
#define QSTR 520                              // half stride per pixel row
#define FSTR 68                               // float stride, per-warp staging
#define PSTR 56                               // half stride, probs

__global__ __launch_bounds__(256, 1)
void attn_kernel(const __half* __restrict__ q,
                 const __half* __restrict__ kv,
                 const float* __restrict__ stat,
                 __half* __restrict__ outp)
{
    extern __shared__ __half smh[];
    __half* sQ = smh;                         // [16][QSTR]
    __half* sK = sQ + Q_L * QSTR;             // [48][QSTR]
    __half* sV = sK + KV_L * QSTR;            // [48][QSTR]
    float*  fB = (float*)(sV + KV_L * QSTR);  // 8 x [16][FSTR]
    __half* sP = (__half*)(fB + 8 * Q_L * FSTR); // 8 x [16][PSTR]

    int tid  = threadIdx.x;
    int wid  = tid >> 5;                      // head
    int lane = tid & 31;
    int win = blockIdx.x;
    int bb  = blockIdx.z;
    int wy = win >> 5, wx = win & 31;
    int d0 = wid * DIM_HEAD;

    // ---- stage q: 16 px x 64 uint4 ----
    for (int i = tid; i < Q_L * 64; i += 256) {
        int pi = i >> 6, v = i & 63;
        int py = pi >> 2, px = pi & 3;
        int pix = (wy * 4 + py) * W_IMG + wx * 4 + px;
        *(uint4*)&sQ[pi * QSTR + v * 8] =
            *(const uint4*)&q[((size_t)bb * HW + pix) * INNER + v * 8];
    }
    // ---- stage k, v: 48 px x 64 uint4 each ----
    for (int i = tid; i < KV_L * 64; i += 256) {
        int j = i >> 6, v = i & 63;
        int f = j >> 4, pi = j & 15;
        int py = pi >> 2, px = pi & 3;
        int pix = (wy * 4 + py) * W_IMG + wx * 4 + px;
        size_t base = ((size_t)(bb * 3 + f) * HW + pix) * (2 * INNER);
        *(uint4*)&sK[j * QSTR + v * 8] = *(const uint4*)&kv[base + v * 8];
        *(uint4*)&sV[j * QSTR + v * 8] = *(const uint4*)&kv[base + INNER + v * 8];
    }
    __syncthreads();

    float*  fbw = fB + wid * Q_L * FSTR;
    __half* spw = sP + wid * Q_L * PSTR;

    // ---- sim = q k^T ----
    wmma::fragment<wmma::accumulator, 16, 16, 16, float> sim[3];
#pragma unroll
    for (int n = 0; n < 3; n++) wmma::fill_fragment(sim[n], 0.0f);
#pragma unroll
    for (int s = 0; s < 4; s++) {
        wmma::fragment<wmma::matrix_a, 16, 16, 16, __half, wmma::row_major> af;
        wmma::load_matrix_sync(af, &sQ[d0 + s * 16], QSTR);
#pragma unroll
        for (int n = 0; n < 3; n++) {
            wmma::fragment<wmma::matrix_b, 16, 16, 16, __half, wmma::col_major> bf;
            wmma::load_matrix_sync(bf, &sK[n * 16 * QSTR + d0 + s * 16], QSTR);
            wmma::mma_sync(sim[n], af, bf, sim[n]);
        }
    }
#pragma unroll
    for (int n = 0; n < 3; n++)
        wmma::store_matrix_sync(&fbw[n * 16], sim[n], FSTR, wmma::mem_row_major);
    __syncwarp();

    // ---- + static_a ----
    for (int e = lane; e < Q_L * KV_L; e += 32) {
        int i = e / KV_L, j = e % KV_L;
        fbw[i * FSTR + j] += stat[((size_t)wid * Q_L + i) * KV_L + j];
    }
    __syncwarp();

    // ---- softmax per row (lanes 0..15) ----
    if (lane < Q_L) {
        float* row = &fbw[lane * FSTR];
        float m = -1e30f;
#pragma unroll
        for (int j = 0; j < KV_L; j++) m = fmaxf(m, row[j]);
        float ssum = 0.f;
#pragma unroll
        for (int j = 0; j < KV_L; j++) {
            float e = expf(row[j] - m);
            row[j] = e; ssum += e;
        }
        float inv = 1.f / ssum;
#pragma unroll
        for (int j = 0; j < KV_L; j++) row[j] *= inv;
    }
    __syncwarp();

    // ---- probs -> fp16 ----
    for (int e = lane; e < Q_L * KV_L; e += 32) {
        int i = e / KV_L, j = e % KV_L;
        spw[i * PSTR + j] = __float2half_rn(fbw[i * FSTR + j]);
    }
    __syncwarp();

    // ---- out = p v ----
    wmma::fragment<wmma::accumulator, 16, 16, 16, float> oacc[4];
#pragma unroll
    for (int n = 0; n < 4; n++) wmma::fill_fragment(oacc[n], 0.0f);
#pragma unroll
    for (int s = 0; s < 3; s++) {
        wmma::fragment<wmma::matrix_a, 16, 16, 16, __half, wmma::row_major> af;
        wmma::load_matrix_sync(af, &spw[s * 16], PSTR);
#pragma unroll
        for (int n = 0; n < 4; n++) {
            wmma::fragment<wmma::matrix_b, 16, 16, 16, __half, wmma::row_major> bf;
            wmma::load_matrix_sync(bf, &sV[s * 16 * QSTR + d0 + n * 16], QSTR);
            wmma::mma_sync(oacc[n], af, bf, oacc[n]);
        }
    }
#pragma unroll
    for (int n = 0; n < 4; n++)
        wmma::store_matrix_sync(&fbw[n * 16], oacc[n], FSTR, wmma::mem_row_major);
    __syncwarp();

    // ---- convert + store (two lanes per row, 32 ch each) ----
    {
        int r  = lane >> 1;
        int hp = lane & 1;
        int py = r >> 2, px = r & 3;
        int pix = (wy * 4 + py) * W_IMG + wx * 4 + px;
        __half* dst = &outp[((size_t)bb * HW + pix) * INNER + d0 + hp * 32];
        const float* srcr = &fbw[r * FSTR + hp * 32];
        __half2 h[16];
#pragma unroll
        for (int t = 0; t < 16; t++)
            h[t] = __floats2half2_rn(srcr[t * 2], srcr[t * 2 + 1]);
#pragma unroll
        for (int t = 0; t < 4; t++)
            *(uint4*)&dst[t * 8] = ((uint4*)h)[t];
    }
}

// ---------------------------------------------------------------------------
// Host launch
// ---------------------------------------------------------------------------
extern "C" void kernel_launch(void* const* d_in, const int* in_sizes, int n_in,
                              void* d_out, int out_size)
{
    (void)in_sizes; (void)n_in; (void)out_size;

    const float* q_inp   = (const float*)d_in[0];
    const float* k_inp   = (const float*)d_in[1];
    const float* flow_f  = (const float*)d_in[2];
    const float* flow_b  = (const float*)d_in[3];
    const float* gq      = (const float*)d_in[4];
    const float* bq      = (const float*)d_in[5];
    const float* gkv     = (const float*)d_in[6];
    const float* bkv     = (const float*)d_in[7];
    const float* Wq      = (const float*)d_in[8];
    const float* Wkv     = (const float*)d_in[9];
    const float* Wout    = (const float*)d_in[10];
    const float* statica = (const float*)d_in[11];

    __half *qn, *kvn, *qb, *kvb, *attb, *wtq, *wtkv, *wtout;
    cudaGetSymbolAddress((void**)&qn,    g_qn);
    cudaGetSymbolAddress((void**)&kvn,   g_kvn);
    cudaGetSymbolAddress((void**)&qb,    g_q);
    cudaGetSymbolAddress((void**)&kvb,   g_kv);
    cudaGetSymbolAddress((void**)&attb,  g_att);
    cudaGetSymbolAddress((void**)&wtq,   g_wt_q);
    cudaGetSymbolAddress((void**)&wtkv,  g_wt_kv);
    cudaGetSymbolAddress((void**)&wtout, g_wt_out);

    const int SMEM4 = ((4 + 2) * 130 * AROWH + 9 * 64 * AROWH) * 2;   // 195,264 B
    const int SMEM2 = ((2 + 2) * 130 * AROWH + 9 * 64 * AROWH) * 2;   // 157,824 B
    const int SMEMA = (Q_L + 2 * KV_L) * QSTR * 2                     // q,k,v
                    + 8 * Q_L * FSTR * 4                              // fp32 staging
                    + 8 * Q_L * PSTR * 2;                             // fp16 probs
    cudaFuncSetAttribute((const void*)conv3x3_h_kernel<4, true>,
                         cudaFuncAttributeMaxDynamicSharedMemorySize, SMEM4);
    cudaFuncSetAttribute((const void*)conv3x3_h_kernel<2, false>,
                         cudaFuncAttributeMaxDynamicSharedMemorySize, SMEM2);
    cudaFuncSetAttribute((const void*)attn_kernel,
                         cudaFuncAttributeMaxDynamicSharedMemorySize, SMEMA);

    // 0) weight transforms (fp16; q-scale 0.125 folded into Wq)
    wtrans_kernel<<<(INNER * C_DIM + 255) / 256, 256>>>(Wq, wtq, INNER, C_DIM, 0.125f);
    wtrans_kernel<<<(2 * INNER * C_DIM + 255) / 256, 256>>>(Wkv, wtkv, 2 * INNER, C_DIM, 1.0f);
    wtrans_kernel<<<(C_DIM * INNER + 255) / 256, 256>>>(Wout, wtout, C_DIM, INNER, 1.0f);

    // 1) layernorm q  (NHWC fp16)
    ln_q_kernel<<<dim3(HW / 128, 1, B), 128>>>(q_inp, gq, bq, qn);

    // 2) warp + stack + layernorm kv  (NHWC fp16)
    warp_ln_kv_kernel<<<dim3(HW / 128, 3, B), 128>>>(k_inp, flow_f, flow_b, gkv, bkv, kvn);

    // 3) conv q: 64 -> 512, NHWC fp16 out (scaled by 0.125)
    conv3x3_h_kernel<4, true><<<dim3(H_IMG / 4, INNER / 64, B), 256, SMEM4>>>(
        qn, wtq, qb, C_DIM, INNER);

    // 4) conv kv: 64 -> 1024, NHWC fp16 out
    conv3x3_h_kernel<4, true><<<dim3(H_IMG / 4, (2 * INNER) / 64, B * 3), 256, SMEM4>>>(
        kvn, wtkv, kvb, C_DIM, 2 * INNER);

    // 5) attention: tensor-core, one block per window
    attn_kernel<<<dim3(1024, 1, B), 256, SMEMA>>>(qb, kvb, statica, attb);

    // 6) conv out: 512 -> 64, fp32 NCHW out -> d_out
    conv3x3_h_kernel<2, false><<<dim3(H_IMG / 2, 1, B), 256, SMEM2>>>(
        attb, wtout, (float*)d_out, INNER, C_DIM);
}